// round 4
// baseline (speedup 1.0000x reference)
#include <cuda_runtime.h>

typedef unsigned long long ull;

#define TILE_E 128
#define K1     214
#define K1P    216
#define SA     132      // A^T row stride (132*4 % 16 == 0 -> LDS.128-aligned rows)
#define HID    128
#define NH2    32
#define NTHR   512

__device__ __forceinline__ ull dup2(float w) {
    ull r;
    asm("mov.b64 %0, {%1, %1};" : "=l"(r) : "f"(w));
    return r;
}
__device__ __forceinline__ void fma2(ull& c, ull a, ull b) {
    asm("fma.rn.f32x2 %0, %1, %2, %0;" : "+l"(c) : "l"(a), "l"(b));
}
__device__ __forceinline__ void unpack2(ull v, float& lo, float& hi) {
    asm("mov.b64 {%0, %1}, %2;" : "=f"(lo), "=f"(hi) : "l"(v));
}

extern "C" __global__ void __launch_bounds__(NTHR, 1)
edge_mlp_kernel(const float* __restrict__ x,
                const float* __restrict__ efeat,
                const float* __restrict__ nodef,
                const float* __restrict__ edgef,
                const int*   __restrict__ src,
                const int*   __restrict__ dst,
                const float* __restrict__ W1,
                const float* __restrict__ b1,
                const float* __restrict__ W2,
                const float* __restrict__ b2,
                const float* __restrict__ W3,
                const float* __restrict__ b3,
                float* __restrict__ out,
                int E)
{
    extern __shared__ float sm[];
    float* As  = sm;               // [K1P][SA]  (reused as h1^T [HID][SA] later)
    float* Ws  = As + K1P * SA;    // [2][8][HID] double-buffered W1 k-chunk
    float* W2T = Ws + 2 * 8 * HID; // [HID][33]  W2 transposed
    float* h2s = W2T + HID * 33;   // [TILE_E][33]

    const int tid   = threadIdx.x;
    const int ebase = blockIdx.x * TILE_E;

    // ---------------- gather A^T tile (coalesced: 16 lanes span one feature row) ---
    {
        const int lane   = tid & 31;
        const int l      = lane & 15;
        const int estart = (tid >> 5) * 2 + (lane >> 4);
        const float4* x4 = (const float4*)x;
        const float4* e4 = (const float4*)efeat;
        const float4  z  = make_float4(0.f, 0.f, 0.f, 0.f);
        for (int eb = estart; eb < TILE_E; eb += 32) {
            const int  eg    = ebase + eb;
            const bool valid = (eg < E);
            int s = 0, d = 0;
            if (valid) { s = src[eg]; d = dst[eg]; }
            const float4 v0 = valid ? x4[s * 16 + l] : z;
            const float4 v1 = valid ? x4[d * 16 + l] : z;
            const float4 v2 = valid ? e4[(size_t)eg * 16 + l] : z;
            const int k0 = 4 * l;
            As[(k0 + 0) * SA + eb] = v0.x;
            As[(k0 + 1) * SA + eb] = v0.y;
            As[(k0 + 2) * SA + eb] = v0.z;
            As[(k0 + 3) * SA + eb] = v0.w;
            As[(64 + k0 + 0) * SA + eb] = v1.x;
            As[(64 + k0 + 1) * SA + eb] = v1.y;
            As[(64 + k0 + 2) * SA + eb] = v1.z;
            As[(64 + k0 + 3) * SA + eb] = v1.w;
            As[(128 + k0 + 0) * SA + eb] = v2.x;
            As[(128 + k0 + 1) * SA + eb] = v2.y;
            As[(128 + k0 + 2) * SA + eb] = v2.z;
            As[(128 + k0 + 3) * SA + eb] = v2.w;
            if (l < 10) {
                As[(192 + l) * SA + eb] = valid ? nodef[s * 10 + l] : 0.f;
                As[(202 + l) * SA + eb] = valid ? nodef[d * 10 + l] : 0.f;
            }
            if (l < 2) {
                As[(212 + l) * SA + eb] = valid ? edgef[(size_t)eg * 2 + l] : 0.f;
                As[(214 + l) * SA + eb] = 0.f;   // K padding rows
            }
        }
    }

    // stage W2^T (disjoint smem region; synced by the layer-1 barriers)
    for (int t = tid; t < HID * NH2; t += NTHR) {
        const int k = t & (HID - 1);
        const int c = t >> 7;
        W2T[k * 33 + c] = W2[c * HID + k];
    }

    // stage W1 chunk 0 into buffer 0
    {
        int t = tid;
        #pragma unroll
        for (int r = 0; r < 2; ++r, t += NTHR) {
            const int j  = t >> 3;
            const int kk = t & 7;
            Ws[kk * HID + j] = W1[j * K1 + kk];
        }
    }
    __syncthreads();

    const int lane = tid & 31;   // hidden group: j = lane + 32*i (lane-distinct W reads)
    const int warp = tid >> 5;   // edge group: whole warp shares 8 edges (broadcast A)
    const int e0   = warp * 8;

    // ---------------- layer 1: [128e][214] @ W1^T -> h1[128e][128], f32x2 packed --
    ull acc[4][4];
    #pragma unroll
    for (int i = 0; i < 4; ++i)
        #pragma unroll
        for (int p = 0; p < 4; ++p) acc[i][p] = 0ull;

    int buf = 0;
    for (int kb = 0; kb < K1P; kb += 8) {
        // prefetch next chunk into registers (overlaps with compute below)
        float r0 = 0.f, r1 = 0.f;
        const bool more = (kb + 8 < K1P);
        if (more) {
            int t = tid;
            int j = t >> 3, kk = t & 7, k = kb + 8 + kk;
            r0 = (k < K1) ? W1[j * K1 + k] : 0.f;
            t += NTHR;
            j = t >> 3; kk = t & 7; k = kb + 8 + kk;
            r1 = (k < K1) ? W1[j * K1 + k] : 0.f;
        }

        const float* Wc = Ws + (buf ? 8 * HID : 0);
        #pragma unroll
        for (int kk = 0; kk < 8; ++kk) {
            const float* arow = As + (kb + kk) * SA + e0;
            const ulonglong2 A01 = *(const ulonglong2*)(arow);      // broadcast LDS.128
            const ulonglong2 A23 = *(const ulonglong2*)(arow + 4);  // broadcast LDS.128
            #pragma unroll
            for (int i = 0; i < 4; ++i) {
                const ull bd = dup2(Wc[kk * HID + lane + 32 * i]);  // lane-distinct LDS.32
                fma2(acc[i][0], A01.x, bd);
                fma2(acc[i][1], A01.y, bd);
                fma2(acc[i][2], A23.x, bd);
                fma2(acc[i][3], A23.y, bd);
            }
        }

        if (more) {
            float* Wn = Ws + (buf ? 0 : 8 * HID);
            int t = tid;
            Wn[(t & 7) * HID + (t >> 3)] = r0;
            t += NTHR;
            Wn[(t & 7) * HID + (t >> 3)] = r1;
        }
        buf ^= 1;
        __syncthreads();   // next chunk ready; also orders final As reads
    }

    // h1 = relu(acc + b1), written back transposed into As
    #pragma unroll
    for (int i = 0; i < 4; ++i) {
        const int   j  = lane + 32 * i;
        const float bj = b1[j];
        #pragma unroll
        for (int p = 0; p < 4; ++p) {
            float lo, hi;
            unpack2(acc[i][p], lo, hi);
            lo = fmaxf(lo + bj, 0.f);
            hi = fmaxf(hi + bj, 0.f);
            *(float2*)(As + j * SA + e0 + 2 * p) = make_float2(lo, hi);
        }
    }
    __syncthreads();

    // ---------------- layer 2: h1[128e][128] @ W2^T -> h2[128e][32] -----------------
    // class c = lane (conflict-free W2T reads), same 8 broadcast edges per warp
    ull acc2[4];
    acc2[0] = acc2[1] = acc2[2] = acc2[3] = 0ull;

    #pragma unroll 4
    for (int k = 0; k < HID; ++k) {
        const float* arow = As + k * SA + e0;
        const ulonglong2 A01 = *(const ulonglong2*)(arow);
        const ulonglong2 A23 = *(const ulonglong2*)(arow + 4);
        const ull bd = dup2(W2T[k * 33 + lane]);
        fma2(acc2[0], A01.x, bd);
        fma2(acc2[1], A01.y, bd);
        fma2(acc2[2], A23.x, bd);
        fma2(acc2[3], A23.y, bd);
    }

    {
        const float bc = b2[lane];
        #pragma unroll
        for (int p = 0; p < 4; ++p) {
            float lo, hi;
            unpack2(acc2[p], lo, hi);
            lo = fmaxf(lo + bc, 0.f);
            hi = fmaxf(hi + bc, 0.f);
            h2s[(e0 + 2 * p) * 33 + lane]     = lo;
            h2s[(e0 + 2 * p + 1) * 33 + lane] = hi;
        }
    }
    __syncthreads();

    // ---------------- layer 3: h2[128e][32] @ W3^T -> out[128e][2] ------------------
    if (tid < TILE_E * 2) {
        const int e   = tid >> 1;
        const int cls = tid & 1;
        float sum = b3[cls];
        #pragma unroll
        for (int k = 0; k < NH2; ++k)
            sum = fmaf(h2s[e * 33 + k], W3[cls * NH2 + k], sum);
        const int eg = ebase + e;
        if (eg < E) out[(size_t)eg * 2 + cls] = sum;
    }
}

extern "C" void kernel_launch(void* const* d_in, const int* in_sizes, int n_in,
                              void* d_out, int out_size) {
    const float* x     = (const float*)d_in[0];
    const float* efeat = (const float*)d_in[1];
    const float* nodef = (const float*)d_in[2];
    const float* edgef = (const float*)d_in[3];
    const int*   src   = (const int*)d_in[4];
    const int*   dst   = (const int*)d_in[5];
    const float* W1    = (const float*)d_in[6];
    const float* b1    = (const float*)d_in[7];
    const float* W2    = (const float*)d_in[8];
    const float* b2    = (const float*)d_in[9];
    const float* W3    = (const float*)d_in[10];
    const float* b3    = (const float*)d_in[11];
    float* out = (float*)d_out;

    const int E = in_sizes[4];   // src element count
    const int blocks = (E + TILE_E - 1) / TILE_E;
    const size_t smem = (size_t)(K1P * SA + 2 * 8 * HID + HID * 33 + TILE_E * 33) * sizeof(float);

    cudaFuncSetAttribute(edge_mlp_kernel,
                         cudaFuncAttributeMaxDynamicSharedMemorySize, (int)smem);

    edge_mlp_kernel<<<blocks, NTHR, smem>>>(x, efeat, nodef, edgef, src, dst,
                                            W1, b1, W2, b2, W3, b3, out, E);
}

// round 6
// speedup vs baseline: 2.3020x; 2.3020x over previous
#include <cuda_runtime.h>
#include <cuda_bf16.h>
#include <cstdint>

typedef uint32_t u32;
typedef unsigned short u16;

#define NTHR   256
#define TILE_E 128
#define K1     214

#define STA  272      // A/h1 row stride bytes (136 bf16) — conflict-free for ldmatrix
#define STW1 464      // W1 row stride (232 bf16) — conflict-free
#define STW2 272

#define OFF_B1S 0
#define OFF_B2S 512
#define OFF_W3S 640
#define OFF_B3S 896
#define OFF_AH  1024
#define OFF_AL  (OFF_AH + 128 * STA)       // 35840
#define OFF_W1H (OFF_AL + 128 * STA)       // 70656
#define OFF_W1L (OFF_W1H + 128 * STW1)     // 130048
#define OFF_W2H (OFF_W1L + 128 * STW1)     // 189440
#define OFF_W2L (OFF_W2H + 32 * STW2)      // 198144
#define OFF_H2  (OFF_W2L + 32 * STW2)      // 206848
#define SMEM_SZ (OFF_H2 + 128 * 136)       // 224256 B

__device__ __forceinline__ u32 s2u(const void* p) {
    u32 a;
    asm("{ .reg .u64 t; cvta.to.shared.u64 t, %1; cvt.u32.u64 %0, t; }" : "=r"(a) : "l"(p));
    return a;
}
__device__ __forceinline__ void ldm4(u32 addr, u32* r) {
    asm volatile("ldmatrix.sync.aligned.m8n8.x4.shared.b16 {%0,%1,%2,%3}, [%4];"
                 : "=r"(r[0]), "=r"(r[1]), "=r"(r[2]), "=r"(r[3]) : "r"(addr));
}
__device__ __forceinline__ void mma_bf16(float* c, const u32* a, u32 b0, u32 b1) {
    asm volatile("mma.sync.aligned.m16n8k16.row.col.f32.bf16.bf16.f32 "
                 "{%0,%1,%2,%3}, {%4,%5,%6,%7}, {%8,%9}, {%0,%1,%2,%3};"
                 : "+f"(c[0]), "+f"(c[1]), "+f"(c[2]), "+f"(c[3])
                 : "r"(a[0]), "r"(a[1]), "r"(a[2]), "r"(a[3]), "r"(b0), "r"(b1));
}
// split (a,b) into packed-bf16x2 hi (truncation) + lo (rounded residual)
__device__ __forceinline__ void splitp(float a, float b, u32& hp, u32& lp) {
    u32 ua = __float_as_uint(a), ub = __float_as_uint(b);
    hp = __byte_perm(ua, ub, 0x7632);
    float ra = a - __uint_as_float(ua & 0xFFFF0000u);
    float rb = b - __uint_as_float(ub & 0xFFFF0000u);
    __nv_bfloat16 la = __float2bfloat16(ra), lb = __float2bfloat16(rb);
    lp = ((u32)(*(u16*)&lb) << 16) | (u32)(*(u16*)&la);
}

template <int NKS>
__device__ __forceinline__ void l1_chunk(float (&acc)[2][8][4],
                                         u32 aBaseH, u32 aBaseL,
                                         u32 bBaseH, u32 bBaseL, u32 bk)
{
    #pragma unroll
    for (int ks = 0; ks < NKS; ++ks) {
        u32 ah[2][4], al[2][4];
        #pragma unroll
        for (int mb = 0; mb < 2; ++mb) {
            ldm4(aBaseH + mb * (16 * STA) + ks * 32, ah[mb]);
            ldm4(aBaseL + mb * (16 * STA) + ks * 32, al[mb]);
        }
        #pragma unroll
        for (int nbp = 0; nbp < 4; ++nbp) {
            u32 bh[4], bl[4];
            ldm4(bBaseH + nbp * (16 * STW1) + bk + ks * 32, bh);
            ldm4(bBaseL + nbp * (16 * STW1) + bk + ks * 32, bl);
            #pragma unroll
            for (int mb = 0; mb < 2; ++mb) {
                mma_bf16(acc[mb][2 * nbp],     ah[mb], bh[0], bh[1]);
                mma_bf16(acc[mb][2 * nbp],     al[mb], bh[0], bh[1]);
                mma_bf16(acc[mb][2 * nbp],     ah[mb], bl[0], bl[1]);
                mma_bf16(acc[mb][2 * nbp + 1], ah[mb], bh[2], bh[3]);
                mma_bf16(acc[mb][2 * nbp + 1], al[mb], bh[2], bh[3]);
                mma_bf16(acc[mb][2 * nbp + 1], ah[mb], bl[2], bl[3]);
            }
        }
    }
}

extern "C" __global__ void __launch_bounds__(NTHR, 1)
edge_mlp_hmma(const float* __restrict__ x, const float* __restrict__ efeat,
              const float* __restrict__ nodef, const float* __restrict__ edgef,
              const int* __restrict__ src, const int* __restrict__ dst,
              const float* __restrict__ W1, const float* __restrict__ b1,
              const float* __restrict__ W2, const float* __restrict__ b2,
              const float* __restrict__ W3, const float* __restrict__ b3,
              float* __restrict__ out, int E, int ntiles)
{
    extern __shared__ char smem[];
    const u32 sb   = s2u(smem);
    const int tid  = threadIdx.x;
    const int wid  = tid >> 5;
    const int lane = tid & 31;

    // ---------- one-time weight staging: split + store [n][k] ----------
    for (int i = tid; i < 128 * 232; i += NTHR) {
        const int j = i / 232, k = i - j * 232;
        const float v = (k < K1) ? W1[j * K1 + k] : 0.f;
        const u32 uv = __float_as_uint(v);
        *(u16*)(smem + OFF_W1H + j * STW1 + k * 2) = (u16)(uv >> 16);
        const float r = v - __uint_as_float(uv & 0xFFFF0000u);
        const __nv_bfloat16 rb = __float2bfloat16(r);
        *(u16*)(smem + OFF_W1L + j * STW1 + k * 2) = *(const u16*)&rb;
    }
    for (int i = tid; i < 32 * 136; i += NTHR) {
        const int j = i / 136, k = i - j * 136;
        const float v = (k < 128) ? W2[j * 128 + k] : 0.f;
        const u32 uv = __float_as_uint(v);
        *(u16*)(smem + OFF_W2H + j * STW2 + k * 2) = (u16)(uv >> 16);
        const float r = v - __uint_as_float(uv & 0xFFFF0000u);
        const __nv_bfloat16 rb = __float2bfloat16(r);
        *(u16*)(smem + OFF_W2L + j * STW2 + k * 2) = *(const u16*)&rb;
    }
    if (tid < 128) ((float*)(smem + OFF_B1S))[tid] = b1[tid];
    if (tid < 32)  ((float*)(smem + OFF_B2S))[tid] = b2[tid];
    if (tid < 64)  ((float*)(smem + OFF_W3S))[tid] = W3[tid];
    if (tid < 2)   ((float*)(smem + OFF_B3S))[tid] = b3[tid];
    __syncthreads();

    // ---------- per-lane fragment address pieces ----------
    const int mg = wid >> 1;       // m-group (32 rows)
    const int nh = wid & 1;        // n-half
    const int aRow  = mg * 32 + ((lane >> 3) & 1) * 8 + (lane & 7);
    const u32 aOff  = (u32)aRow * STA + (u32)(lane >> 4) * 16;
    const u32 aBH   = sb + OFF_AH + aOff;
    const u32 aBL   = sb + OFF_AL + aOff;
    const int bSel  = lane >> 4, bKh = (lane >> 3) & 1, bRow = lane & 7;
    const u32 b1off = (u32)(nh * 64 + bSel * 8 + bRow) * STW1 + (u32)bKh * 16;
    const u32 b1H   = sb + OFF_W1H + b1off;
    const u32 b1L   = sb + OFF_W1L + b1off;
    const u32 b2off = (u32)(nh * 16 + bSel * 8 + bRow) * STW2 + (u32)bKh * 16;
    const u32 b2H   = sb + OFF_W2H + b2off;
    const u32 b2L   = sb + OFF_W2L + b2off;

    const float* b1s = (const float*)(smem + OFF_B1S);
    const float* b2s = (const float*)(smem + OFF_B2S);
    const float* W3s = (const float*)(smem + OFF_W3S);
    const float* b3s = (const float*)(smem + OFF_B3S);
    float* h2s = (float*)(smem + OFF_H2);   // [128][34] f32

    const int gm = tid >> 1, gq = tid & 1;  // gather mapping

    for (int tile = blockIdx.x; tile < ntiles; tile += gridDim.x) {
        const int ebase = tile * TILE_E;

        // ---------- gather chunk 0: k 0..127 = x[src](64) ++ x[dst](64) ----------
        {
            const int  eg = ebase + gm;
            const bool ve = eg < E;
            const int  sN = ve ? src[eg] : 0;
            const int  dN = ve ? dst[eg] : 0;
            const float4* p = (const float4*)(x + (size_t)(gq ? dN : sN) * 64);
            const u32 wb = (u32)gm * STA + (u32)gq * 128;
            #pragma unroll
            for (int t8 = 0; t8 < 8; ++t8) {
                const float4 va = p[2 * t8], vb = p[2 * t8 + 1];
                uint4 hv, lv;
                splitp(va.x, va.y, hv.x, lv.x);
                splitp(va.z, va.w, hv.y, lv.y);
                splitp(vb.x, vb.y, hv.z, lv.z);
                splitp(vb.z, vb.w, hv.w, lv.w);
                *(uint4*)(smem + OFF_AH + wb + t8 * 16) = hv;
                *(uint4*)(smem + OFF_AL + wb + t8 * 16) = lv;
            }
        }
        __syncthreads();

        float acc[2][8][4];
        #pragma unroll
        for (int i = 0; i < 2; ++i)
            #pragma unroll
            for (int j = 0; j < 8; ++j)
                #pragma unroll
                for (int p = 0; p < 4; ++p) acc[i][j][p] = 0.f;

        l1_chunk<8>(acc, aBH, aBL, b1H, b1L, 0);
        __syncthreads();

        // ---------- gather chunk 1: k 128..223 = e(64) ++ nf_s(10) nf_d(10) ef(2) pad ----------
        {
            const int  eg  = ebase + gm;
            const bool ve  = eg < E;
            const size_t egc = ve ? (size_t)eg : 0;
            const u32 wb = (u32)gm * STA;
            if (gq == 0) {
                const float4* p = (const float4*)(efeat + egc * 64);
                #pragma unroll
                for (int t8 = 0; t8 < 8; ++t8) {
                    const float4 va = p[2 * t8], vb = p[2 * t8 + 1];
                    uint4 hv, lv;
                    splitp(va.x, va.y, hv.x, lv.x);
                    splitp(va.z, va.w, hv.y, lv.y);
                    splitp(vb.x, vb.y, hv.z, lv.z);
                    splitp(vb.z, vb.w, hv.w, lv.w);
                    *(uint4*)(smem + OFF_AH + wb + t8 * 16) = hv;
                    *(uint4*)(smem + OFF_AL + wb + t8 * 16) = lv;
                }
            } else {
                const int sN = ve ? src[eg] : 0;
                const int dN = ve ? dst[eg] : 0;
                float v[32];
                #pragma unroll
                for (int j = 0; j < 10; ++j) {
                    v[j]      = nodef[(size_t)sN * 10 + j];
                    v[10 + j] = nodef[(size_t)dN * 10 + j];
                }
                v[20] = edgef[egc * 2];
                v[21] = edgef[egc * 2 + 1];
                #pragma unroll
                for (int j = 22; j < 32; ++j) v[j] = 0.f;
                #pragma unroll
                for (int t8 = 0; t8 < 4; ++t8) {
                    uint4 hv, lv;
                    splitp(v[8 * t8 + 0], v[8 * t8 + 1], hv.x, lv.x);
                    splitp(v[8 * t8 + 2], v[8 * t8 + 3], hv.y, lv.y);
                    splitp(v[8 * t8 + 4], v[8 * t8 + 5], hv.z, lv.z);
                    splitp(v[8 * t8 + 6], v[8 * t8 + 7], hv.w, lv.w);
                    *(uint4*)(smem + OFF_AH + wb + 128 + t8 * 16) = hv;
                    *(uint4*)(smem + OFF_AL + wb + 128 + t8 * 16) = lv;
                }
            }
        }
        __syncthreads();

        l1_chunk<6>(acc, aBH, aBL, b1H, b1L, 8 * 32);
        __syncthreads();

        // ---------- epilogue 1: bias + relu + split -> h1 into A buffers ----------
        #pragma unroll
        for (int mb = 0; mb < 2; ++mb) {
            const int r0 = mg * 32 + mb * 16 + (lane >> 2);
            #pragma unroll
            for (int nbl = 0; nbl < 8; ++nbl) {
                const int n0 = (nh * 8 + nbl) * 8 + 2 * (lane & 3);
                const float bb0 = b1s[n0], bb1 = b1s[n0 + 1];
                float f0 = fmaxf(acc[mb][nbl][0] + bb0, 0.f);
                float f1 = fmaxf(acc[mb][nbl][1] + bb1, 0.f);
                u32 hp, lp;
                splitp(f0, f1, hp, lp);
                *(u32*)(smem + OFF_AH + r0 * STA + n0 * 2) = hp;
                *(u32*)(smem + OFF_AL + r0 * STA + n0 * 2) = lp;
                f0 = fmaxf(acc[mb][nbl][2] + bb0, 0.f);
                f1 = fmaxf(acc[mb][nbl][3] + bb1, 0.f);
                splitp(f0, f1, hp, lp);
                *(u32*)(smem + OFF_AH + (r0 + 8) * STA + n0 * 2) = hp;
                *(u32*)(smem + OFF_AL + (r0 + 8) * STA + n0 * 2) = lp;
            }
        }
        __syncthreads();

        // ---------- layer 2: h1[128x128] @ W2^T -> h2[128x32] ----------
        float acc2[2][2][4];
        #pragma unroll
        for (int i = 0; i < 2; ++i)
            #pragma unroll
            for (int j = 0; j < 2; ++j)
                #pragma unroll
                for (int p = 0; p < 4; ++p) acc2[i][j][p] = 0.f;

        #pragma unroll
        for (int ks = 0; ks < 8; ++ks) {
            u32 ah[2][4], al[2][4];
            #pragma unroll
            for (int mb = 0; mb < 2; ++mb) {
                ldm4(aBH + mb * (16 * STA) + ks * 32, ah[mb]);
                ldm4(aBL + mb * (16 * STA) + ks * 32, al[mb]);
            }
            u32 bh[4], bl[4];
            ldm4(b2H + ks * 32, bh);
            ldm4(b2L + ks * 32, bl);
            #pragma unroll
            for (int mb = 0; mb < 2; ++mb) {
                mma_bf16(acc2[mb][0], ah[mb], bh[0], bh[1]);
                mma_bf16(acc2[mb][0], al[mb], bh[0], bh[1]);
                mma_bf16(acc2[mb][0], ah[mb], bl[0], bl[1]);
                mma_bf16(acc2[mb][1], ah[mb], bh[2], bh[3]);
                mma_bf16(acc2[mb][1], al[mb], bh[2], bh[3]);
                mma_bf16(acc2[mb][1], ah[mb], bl[2], bl[3]);
            }
        }

        // ---------- epilogue 2: bias + relu -> h2s ----------
        #pragma unroll
        for (int mb = 0; mb < 2; ++mb) {
            const int r0 = mg * 32 + mb * 16 + (lane >> 2);
            #pragma unroll
            for (int nbl = 0; nbl < 2; ++nbl) {
                const int c0 = (nh * 2 + nbl) * 8 + 2 * (lane & 3);
                const float bb0 = b2s[c0], bb1 = b2s[c0 + 1];
                *(float2*)(h2s + r0 * 34 + c0) =
                    make_float2(fmaxf(acc2[mb][nbl][0] + bb0, 0.f),
                                fmaxf(acc2[mb][nbl][1] + bb1, 0.f));
                *(float2*)(h2s + (r0 + 8) * 34 + c0) =
                    make_float2(fmaxf(acc2[mb][nbl][2] + bb0, 0.f),
                                fmaxf(acc2[mb][nbl][3] + bb1, 0.f));
            }
        }
        __syncthreads();

        // ---------- layer 3: h2[128x32] @ W3^T + b3 -> out ----------
        {
            const int row = tid >> 1, cls = tid & 1;
            float sum = b3s[cls];
            #pragma unroll
            for (int k = 0; k < 32; ++k)
                sum = fmaf(h2s[row * 34 + k], W3s[cls * 32 + k], sum);
            const int eg = ebase + row;
            if (eg < E) out[(size_t)eg * 2 + cls] = sum;
        }
        __syncthreads();
    }
}

extern "C" void kernel_launch(void* const* d_in, const int* in_sizes, int n_in,
                              void* d_out, int out_size) {
    const float* x     = (const float*)d_in[0];
    const float* efeat = (const float*)d_in[1];
    const float* nodef = (const float*)d_in[2];
    const float* edgef = (const float*)d_in[3];
    const int*   src   = (const int*)d_in[4];
    const int*   dst   = (const int*)d_in[5];
    const float* W1    = (const float*)d_in[6];
    const float* b1    = (const float*)d_in[7];
    const float* W2    = (const float*)d_in[8];
    const float* b2    = (const float*)d_in[9];
    const float* W3    = (const float*)d_in[10];
    const float* b3    = (const float*)d_in[11];
    float* out = (float*)d_out;

    const int E      = in_sizes[4];
    const int ntiles = (E + TILE_E - 1) / TILE_E;

    cudaFuncSetAttribute(edge_mlp_hmma, cudaFuncAttributeMaxDynamicSharedMemorySize, SMEM_SZ);
    int grid = 152;
    if (grid > ntiles) grid = ntiles;
    edge_mlp_hmma<<<grid, NTHR, SMEM_SZ>>>(x, efeat, nodef, edgef, src, dst,
                                           W1, b1, W2, b2, W3, b3, out, E, ntiles);
}

// round 7
// speedup vs baseline: 2.3096x; 1.0033x over previous
#include <cuda_runtime.h>
#include <cuda_bf16.h>
#include <cstdint>

typedef uint32_t u32;
typedef unsigned short u16;

#define NTHR   512
#define TILE_E 128
#define K1     214

#define STA  272      // A/h1 row stride bytes (136 bf16)
#define STW1 464      // W1 row stride (232 bf16)
#define STW2 272

#define OFF_B1S 0
#define OFF_B2S 512
#define OFF_W3S 640
#define OFF_B3S 896
#define OFF_AH  1024
#define OFF_AL  (OFF_AH + 128 * STA)
#define OFF_W1H (OFF_AL + 128 * STA)
#define OFF_W1L (OFF_W1H + 128 * STW1)
#define OFF_W2H (OFF_W1L + 128 * STW1)
#define OFF_W2L (OFF_W2H + 32 * STW2)
#define OFF_H2  (OFF_W2L + 32 * STW2)
#define SMEM_SZ (OFF_H2 + 128 * 136)       // 224256 B

__device__ __forceinline__ u32 s2u(const void* p) {
    u32 a;
    asm("{ .reg .u64 t; cvta.to.shared.u64 t, %1; cvt.u32.u64 %0, t; }" : "=r"(a) : "l"(p));
    return a;
}
__device__ __forceinline__ void ldm4(u32 addr, u32* r) {
    asm volatile("ldmatrix.sync.aligned.m8n8.x4.shared.b16 {%0,%1,%2,%3}, [%4];"
                 : "=r"(r[0]), "=r"(r[1]), "=r"(r[2]), "=r"(r[3]) : "r"(addr));
}
__device__ __forceinline__ void ldm2(u32 addr, u32* r) {
    asm volatile("ldmatrix.sync.aligned.m8n8.x2.shared.b16 {%0,%1}, [%2];"
                 : "=r"(r[0]), "=r"(r[1]) : "r"(addr));
}
__device__ __forceinline__ void mma_bf16(float* c, const u32* a, u32 b0, u32 b1) {
    asm volatile("mma.sync.aligned.m16n8k16.row.col.f32.bf16.bf16.f32 "
                 "{%0,%1,%2,%3}, {%4,%5,%6,%7}, {%8,%9}, {%0,%1,%2,%3};"
                 : "+f"(c[0]), "+f"(c[1]), "+f"(c[2]), "+f"(c[3])
                 : "r"(a[0]), "r"(a[1]), "r"(a[2]), "r"(a[3]), "r"(b0), "r"(b1));
}
// split (a,b) into packed-bf16x2 hi (truncation) + lo (rounded residual)
__device__ __forceinline__ void splitp(float a, float b, u32& hp, u32& lp) {
    u32 ua = __float_as_uint(a), ub = __float_as_uint(b);
    hp = __byte_perm(ua, ub, 0x7632);
    float ra = a - __uint_as_float(ua & 0xFFFF0000u);
    float rb = b - __uint_as_float(ub & 0xFFFF0000u);
    __nv_bfloat16 la = __float2bfloat16(ra), lb = __float2bfloat16(rb);
    lp = ((u32)(*(u16*)&lb) << 16) | (u32)(*(u16*)&la);
}

// layer-1 chunk: warp computes 32 rows x 32 cols; NKS k-steps of 16; bk = B k-byte offset
template <int NKS>
__device__ __forceinline__ void l1_chunk(float (&acc)[2][4][4],
                                         u32 aBH, u32 aBL,
                                         u32 b1H, u32 b1L, u32 bk)
{
    #pragma unroll
    for (int ks = 0; ks < NKS; ++ks) {
        u32 ah[2][4], al[2][4];
        #pragma unroll
        for (int mb = 0; mb < 2; ++mb) {
            ldm4(aBH + mb * (16 * STA) + ks * 32, ah[mb]);
            ldm4(aBL + mb * (16 * STA) + ks * 32, al[mb]);
        }
        #pragma unroll
        for (int np = 0; np < 2; ++np) {
            u32 bh[4], bl[4];
            ldm4(b1H + np * (16 * STW1) + bk + ks * 32, bh);
            ldm4(b1L + np * (16 * STW1) + bk + ks * 32, bl);
            #pragma unroll
            for (int mb = 0; mb < 2; ++mb) {
                mma_bf16(acc[mb][2 * np],     ah[mb], bh[0], bh[1]);
                mma_bf16(acc[mb][2 * np],     al[mb], bh[0], bh[1]);
                mma_bf16(acc[mb][2 * np],     ah[mb], bl[0], bl[1]);
                mma_bf16(acc[mb][2 * np + 1], ah[mb], bh[2], bh[3]);
                mma_bf16(acc[mb][2 * np + 1], al[mb], bh[2], bh[3]);
                mma_bf16(acc[mb][2 * np + 1], ah[mb], bl[2], bl[3]);
            }
        }
    }
}

extern "C" __global__ void __launch_bounds__(NTHR, 1)
edge_mlp_hmma(const float* __restrict__ x, const float* __restrict__ efeat,
              const float* __restrict__ nodef, const float* __restrict__ edgef,
              const int* __restrict__ src, const int* __restrict__ dst,
              const float* __restrict__ W1, const float* __restrict__ b1,
              const float* __restrict__ W2, const float* __restrict__ b2,
              const float* __restrict__ W3, const float* __restrict__ b3,
              float* __restrict__ out, int E, int ntiles)
{
    extern __shared__ char smem[];
    const u32 sb   = s2u(smem);
    const int tid  = threadIdx.x;
    const int wid  = tid >> 5;
    const int lane = tid & 31;

    // ---------- one-time weight staging: split + store [n][k] ----------
    for (int i = tid; i < 128 * 232; i += NTHR) {
        const int j = i / 232, k = i - j * 232;
        const float v = (k < K1) ? W1[j * K1 + k] : 0.f;
        const u32 uv = __float_as_uint(v);
        *(u16*)(smem + OFF_W1H + j * STW1 + k * 2) = (u16)(uv >> 16);
        const float r = v - __uint_as_float(uv & 0xFFFF0000u);
        const __nv_bfloat16 rb = __float2bfloat16(r);
        *(u16*)(smem + OFF_W1L + j * STW1 + k * 2) = *(const u16*)&rb;
    }
    for (int i = tid; i < 32 * 136; i += NTHR) {
        const int j = i / 136, k = i - j * 136;
        const float v = (k < 128) ? W2[j * 128 + k] : 0.f;
        const u32 uv = __float_as_uint(v);
        *(u16*)(smem + OFF_W2H + j * STW2 + k * 2) = (u16)(uv >> 16);
        const float r = v - __uint_as_float(uv & 0xFFFF0000u);
        const __nv_bfloat16 rb = __float2bfloat16(r);
        *(u16*)(smem + OFF_W2L + j * STW2 + k * 2) = *(const u16*)&rb;
    }
    if (tid < 128) ((float*)(smem + OFF_B1S))[tid] = b1[tid];
    if (tid < 32)  ((float*)(smem + OFF_B2S))[tid] = b2[tid];
    if (tid < 64)  ((float*)(smem + OFF_W3S))[tid] = W3[tid];
    if (tid < 2)   ((float*)(smem + OFF_B3S))[tid] = b3[tid];
    __syncthreads();

    // ---------- per-lane fragment addresses ----------
    const int mg = wid >> 2;       // m-group: rows mg*32 .. +31
    const int nq = wid & 3;        // n-quarter: layer1 cols nq*32 .. +31; layer2 cols nq*8
    const int aRow = mg * 32 + ((lane >> 3) & 1) * 8 + (lane & 7);
    const u32 aOff = (u32)aRow * STA + (u32)(lane >> 4) * 16;
    const u32 aBH  = sb + OFF_AH + aOff;
    const u32 aBL  = sb + OFF_AL + aOff;
    const int bSel = lane >> 4, bKh = (lane >> 3) & 1, bRow = lane & 7;
    const u32 b1off = (u32)(nq * 32 + bSel * 8 + bRow) * STW1 + (u32)bKh * 16;
    const u32 b1H  = sb + OFF_W1H + b1off;
    const u32 b1L  = sb + OFF_W1L + b1off;
    const u32 b2off = (u32)(nq * 8 + (lane & 7)) * STW2 + (u32)((lane >> 3) & 1) * 16;
    const u32 b2H  = sb + OFF_W2H + b2off;
    const u32 b2L  = sb + OFF_W2L + b2off;

    const float* b1s = (const float*)(smem + OFF_B1S);
    const float* b2s = (const float*)(smem + OFF_B2S);
    const float* W3s = (const float*)(smem + OFF_W3S);
    const float* b3s = (const float*)(smem + OFF_B3S);
    float* h2s = (float*)(smem + OFF_H2);   // [128][34] f32

    const int gm = tid >> 2, gq = tid & 3;  // gather: 4 threads per edge

    for (int tile = blockIdx.x; tile < ntiles; tile += gridDim.x) {
        const int ebase = tile * TILE_E;
        const int  eg  = ebase + gm;
        const bool ve  = eg < E;
        const size_t egc = ve ? (size_t)eg : 0;
        const int sN = ve ? src[eg] : 0;
        const int dN = ve ? dst[eg] : 0;

        // ---------- gather chunk 0: k 0..127 = x[src](64) ++ x[dst](64) ----------
        {
            const float4* p = (const float4*)((gq < 2) ? (x + (size_t)sN * 64 + gq * 32)
                                                       : (x + (size_t)dN * 64 + (gq - 2) * 32));
            const u32 wb = (u32)gm * STA + (u32)gq * 64;
            #pragma unroll
            for (int t8 = 0; t8 < 4; ++t8) {
                const float4 va = p[2 * t8], vb = p[2 * t8 + 1];
                uint4 hv, lv;
                splitp(va.x, va.y, hv.x, lv.x);
                splitp(va.z, va.w, hv.y, lv.y);
                splitp(vb.x, vb.y, hv.z, lv.z);
                splitp(vb.z, vb.w, hv.w, lv.w);
                *(uint4*)(smem + OFF_AH + wb + t8 * 16) = hv;
                *(uint4*)(smem + OFF_AL + wb + t8 * 16) = lv;
            }
        }
        __syncthreads();

        float acc[2][4][4];
        #pragma unroll
        for (int i = 0; i < 2; ++i)
            #pragma unroll
            for (int j = 0; j < 4; ++j)
                #pragma unroll
                for (int p = 0; p < 4; ++p) acc[i][j][p] = 0.f;

        l1_chunk<8>(acc, aBH, aBL, b1H, b1L, 0);
        __syncthreads();

        // ---------- gather chunk 1: k 128..223 = e(64) ++ nf_s(10) nf_d(10) ef(2) pad ----------
        if (gq < 2) {
            const float4* p = (const float4*)(efeat + egc * 64 + gq * 32);
            const u32 wb = (u32)gm * STA + (u32)gq * 64;
            #pragma unroll
            for (int t8 = 0; t8 < 4; ++t8) {
                const float4 va = p[2 * t8], vb = p[2 * t8 + 1];
                uint4 hv, lv;
                splitp(va.x, va.y, hv.x, lv.x);
                splitp(va.z, va.w, hv.y, lv.y);
                splitp(vb.x, vb.y, hv.z, lv.z);
                splitp(vb.z, vb.w, hv.w, lv.w);
                *(uint4*)(smem + OFF_AH + wb + t8 * 16) = hv;
                *(uint4*)(smem + OFF_AL + wb + t8 * 16) = lv;
            }
        } else if (gq == 2) {
            float v[32];
            #pragma unroll
            for (int j = 0; j < 10; ++j) {
                v[j]      = nodef[(size_t)sN * 10 + j];
                v[10 + j] = nodef[(size_t)dN * 10 + j];
            }
            v[20] = edgef[egc * 2];
            v[21] = edgef[egc * 2 + 1];
            #pragma unroll
            for (int j = 22; j < 32; ++j) v[j] = 0.f;
            const u32 wb = (u32)gm * STA + 128;
            #pragma unroll
            for (int t8 = 0; t8 < 4; ++t8) {
                uint4 hv, lv;
                splitp(v[8 * t8 + 0], v[8 * t8 + 1], hv.x, lv.x);
                splitp(v[8 * t8 + 2], v[8 * t8 + 3], hv.y, lv.y);
                splitp(v[8 * t8 + 4], v[8 * t8 + 5], hv.z, lv.z);
                splitp(v[8 * t8 + 6], v[8 * t8 + 7], hv.w, lv.w);
                *(uint4*)(smem + OFF_AH + wb + t8 * 16) = hv;
                *(uint4*)(smem + OFF_AL + wb + t8 * 16) = lv;
            }
        }
        __syncthreads();

        l1_chunk<6>(acc, aBH, aBL, b1H, b1L, 8 * 32);
        __syncthreads();

        // ---------- epilogue 1: bias + relu + split -> h1 into A buffers ----------
        #pragma unroll
        for (int mb = 0; mb < 2; ++mb) {
            const int r0 = mg * 32 + mb * 16 + (lane >> 2);
            #pragma unroll
            for (int nbl = 0; nbl < 4; ++nbl) {
                const int n0 = nq * 32 + nbl * 8 + 2 * (lane & 3);
                const float bb0 = b1s[n0], bb1 = b1s[n0 + 1];
                float f0 = fmaxf(acc[mb][nbl][0] + bb0, 0.f);
                float f1 = fmaxf(acc[mb][nbl][1] + bb1, 0.f);
                u32 hp, lp;
                splitp(f0, f1, hp, lp);
                *(u32*)(smem + OFF_AH + r0 * STA + n0 * 2) = hp;
                *(u32*)(smem + OFF_AL + r0 * STA + n0 * 2) = lp;
                f0 = fmaxf(acc[mb][nbl][2] + bb0, 0.f);
                f1 = fmaxf(acc[mb][nbl][3] + bb1, 0.f);
                splitp(f0, f1, hp, lp);
                *(u32*)(smem + OFF_AH + (r0 + 8) * STA + n0 * 2) = hp;
                *(u32*)(smem + OFF_AL + (r0 + 8) * STA + n0 * 2) = lp;
            }
        }
        __syncthreads();

        // ---------- layer 2: h1[128x128] @ W2^T -> h2[128x32]; warp owns 32r x 8c ----------
        float acc2[2][4];
        #pragma unroll
        for (int i = 0; i < 2; ++i)
            #pragma unroll
            for (int p = 0; p < 4; ++p) acc2[i][p] = 0.f;

        #pragma unroll
        for (int ks = 0; ks < 8; ++ks) {
            u32 ah[2][4], al[2][4];
            #pragma unroll
            for (int mb = 0; mb < 2; ++mb) {
                ldm4(aBH + mb * (16 * STA) + ks * 32, ah[mb]);
                ldm4(aBL + mb * (16 * STA) + ks * 32, al[mb]);
            }
            u32 bh[2], bl[2];
            ldm2(b2H + ks * 32, bh);
            ldm2(b2L + ks * 32, bl);
            #pragma unroll
            for (int mb = 0; mb < 2; ++mb) {
                mma_bf16(acc2[mb], ah[mb], bh[0], bh[1]);
                mma_bf16(acc2[mb], al[mb], bh[0], bh[1]);
                mma_bf16(acc2[mb], ah[mb], bl[0], bl[1]);
            }
        }

        // ---------- epilogue 2: bias + relu -> h2s ----------
        #pragma unroll
        for (int mb = 0; mb < 2; ++mb) {
            const int r0 = mg * 32 + mb * 16 + (lane >> 2);
            const int c0 = nq * 8 + 2 * (lane & 3);
            const float bb0 = b2s[c0], bb1 = b2s[c0 + 1];
            *(float2*)(h2s + r0 * 34 + c0) =
                make_float2(fmaxf(acc2[mb][0] + bb0, 0.f),
                            fmaxf(acc2[mb][1] + bb1, 0.f));
            *(float2*)(h2s + (r0 + 8) * 34 + c0) =
                make_float2(fmaxf(acc2[mb][2] + bb0, 0.f),
                            fmaxf(acc2[mb][3] + bb1, 0.f));
        }
        __syncthreads();

        // ---------- layer 3: h2[128x32] @ W3^T + b3 -> out ----------
        if (tid < TILE_E * 2) {
            const int row = tid >> 1, cls = tid & 1;
            float sum = b3s[cls];
            #pragma unroll
            for (int k = 0; k < 32; ++k)
                sum = fmaf(h2s[row * 34 + k], W3s[cls * 32 + k], sum);
            const int ego = ebase + row;
            if (ego < E) out[(size_t)ego * 2 + cls] = sum;
        }
        __syncthreads();
    }
}

extern "C" void kernel_launch(void* const* d_in, const int* in_sizes, int n_in,
                              void* d_out, int out_size) {
    const float* x     = (const float*)d_in[0];
    const float* efeat = (const float*)d_in[1];
    const float* nodef = (const float*)d_in[2];
    const float* edgef = (const float*)d_in[3];
    const int*   src   = (const int*)d_in[4];
    const int*   dst   = (const int*)d_in[5];
    const float* W1    = (const float*)d_in[6];
    const float* b1    = (const float*)d_in[7];
    const float* W2    = (const float*)d_in[8];
    const float* b2    = (const float*)d_in[9];
    const float* W3    = (const float*)d_in[10];
    const float* b3    = (const float*)d_in[11];
    float* out = (float*)d_out;

    const int E      = in_sizes[4];
    const int ntiles = (E + TILE_E - 1) / TILE_E;

    cudaFuncSetAttribute(edge_mlp_hmma, cudaFuncAttributeMaxDynamicSharedMemorySize, SMEM_SZ);
    int grid = 152;
    if (grid > ntiles) grid = ntiles;
    edge_mlp_hmma<<<grid, NTHR, SMEM_SZ>>>(x, efeat, nodef, edgef, src, dst,
                                           W1, b1, W2, b2, W3, b3, out, E, ntiles);
}

// round 8
// speedup vs baseline: 2.4062x; 1.0418x over previous
#include <cuda_runtime.h>
#include <cuda_bf16.h>
#include <cstdint>

typedef uint32_t u32;
typedef unsigned short u16;

#define NTHR   512
#define TILE_E 128
#define K1     214

#define STA  272      // A/h1 row stride bytes (136 bf16)
#define STW1 464      // W1 row stride (232 bf16)
#define STW2 272

#define OFF_B1S 0
#define OFF_B2S 512
#define OFF_W3S 640
#define OFF_B3S 896
#define OFF_AH  1024
#define OFF_AL  (OFF_AH + 128 * STA)
#define OFF_W1H (OFF_AL + 128 * STA)
#define OFF_W1L (OFF_W1H + 128 * STW1)
#define OFF_W2H (OFF_W1L + 128 * STW1)
#define OFF_W2L (OFF_W2H + 32 * STW2)
#define OFF_H2  (OFF_W2L + 32 * STW2)
#define SMEM_SZ (OFF_H2 + 128 * 136)       // 224256 B

__device__ __forceinline__ u32 s2u(const void* p) {
    u32 a;
    asm("{ .reg .u64 t; cvta.to.shared.u64 t, %1; cvt.u32.u64 %0, t; }" : "=r"(a) : "l"(p));
    return a;
}
__device__ __forceinline__ void ldm4(u32 addr, u32* r) {
    asm volatile("ldmatrix.sync.aligned.m8n8.x4.shared.b16 {%0,%1,%2,%3}, [%4];"
                 : "=r"(r[0]), "=r"(r[1]), "=r"(r[2]), "=r"(r[3]) : "r"(addr));
}
__device__ __forceinline__ void ldm2(u32 addr, u32* r) {
    asm volatile("ldmatrix.sync.aligned.m8n8.x2.shared.b16 {%0,%1}, [%2];"
                 : "=r"(r[0]), "=r"(r[1]) : "r"(addr));
}
__device__ __forceinline__ void mma_bf16(float* c, const u32* a, u32 b0, u32 b1) {
    asm volatile("mma.sync.aligned.m16n8k16.row.col.f32.bf16.bf16.f32 "
                 "{%0,%1,%2,%3}, {%4,%5,%6,%7}, {%8,%9}, {%0,%1,%2,%3};"
                 : "+f"(c[0]), "+f"(c[1]), "+f"(c[2]), "+f"(c[3])
                 : "r"(a[0]), "r"(a[1]), "r"(a[2]), "r"(a[3]), "r"(b0), "r"(b1));
}
// split (a,b) into packed-bf16x2 hi (truncation) + lo (rounded residual)
__device__ __forceinline__ void splitp(float a, float b, u32& hp, u32& lp) {
    u32 ua = __float_as_uint(a), ub = __float_as_uint(b);
    hp = __byte_perm(ua, ub, 0x7632);
    float ra = a - __uint_as_float(ua & 0xFFFF0000u);
    float rb = b - __uint_as_float(ub & 0xFFFF0000u);
    __nv_bfloat16 la = __float2bfloat16(ra), lb = __float2bfloat16(rb);
    lp = ((u32)(*(u16*)&lb) << 16) | (u32)(*(u16*)&la);
}
// split 8 floats (2 float4) and store 16B hi + 16B lo at swiz offset
__device__ __forceinline__ void sts_split8(char* smem, u32 wb, const float* v) {
    uint4 hv, lv;
    splitp(v[0], v[1], hv.x, lv.x);
    splitp(v[2], v[3], hv.y, lv.y);
    splitp(v[4], v[5], hv.z, lv.z);
    splitp(v[6], v[7], hv.w, lv.w);
    *(uint4*)(smem + OFF_AH + wb) = hv;
    *(uint4*)(smem + OFF_AL + wb) = lv;
}

// layer-1 chunk: warp computes 32 rows x 32 cols; NKS k-steps of 16; bk = B k-byte offset
template <int NKS>
__device__ __forceinline__ void l1_chunk(float (&acc)[2][4][4],
                                         u32 aBH, u32 aBL,
                                         u32 b1H, u32 b1L, u32 bk)
{
    #pragma unroll
    for (int ks = 0; ks < NKS; ++ks) {
        u32 ah[2][4], al[2][4];
        #pragma unroll
        for (int mb = 0; mb < 2; ++mb) {
            ldm4(aBH + mb * (16 * STA) + ks * 32, ah[mb]);
            ldm4(aBL + mb * (16 * STA) + ks * 32, al[mb]);
        }
        #pragma unroll
        for (int np = 0; np < 2; ++np) {
            u32 bh[4], bl[4];
            ldm4(b1H + np * (16 * STW1) + bk + ks * 32, bh);
            ldm4(b1L + np * (16 * STW1) + bk + ks * 32, bl);
            #pragma unroll
            for (int mb = 0; mb < 2; ++mb) {
                mma_bf16(acc[mb][2 * np],     ah[mb], bh[0], bh[1]);
                mma_bf16(acc[mb][2 * np],     al[mb], bh[0], bh[1]);
                mma_bf16(acc[mb][2 * np],     ah[mb], bl[0], bl[1]);
                mma_bf16(acc[mb][2 * np + 1], ah[mb], bh[2], bh[3]);
                mma_bf16(acc[mb][2 * np + 1], al[mb], bh[2], bh[3]);
                mma_bf16(acc[mb][2 * np + 1], ah[mb], bl[2], bl[3]);
            }
        }
    }
}

extern "C" __global__ void __launch_bounds__(NTHR, 1)
edge_mlp_hmma(const float* __restrict__ x, const float* __restrict__ efeat,
              const float* __restrict__ nodef, const float* __restrict__ edgef,
              const int* __restrict__ src, const int* __restrict__ dst,
              const float* __restrict__ W1, const float* __restrict__ b1,
              const float* __restrict__ W2, const float* __restrict__ b2,
              const float* __restrict__ W3, const float* __restrict__ b3,
              float* __restrict__ out, int E, int ntiles)
{
    extern __shared__ char smem[];
    const u32 sb   = s2u(smem);
    const int tid  = threadIdx.x;
    const int wid  = tid >> 5;
    const int lane = tid & 31;

    const int gm = tid >> 2, gq = tid & 3;  // gather: 4 threads per edge

    // ---------- initial prefetch: tile-0 indices + chunk0 into registers ----------
    int sN, dN;
    bool ve;
    float4 rc0[8];
    {
        const int eg = blockIdx.x * TILE_E + gm;
        ve = eg < E;
        sN = ve ? src[eg] : 0;
        dN = ve ? dst[eg] : 0;
        const float4* p = (const float4*)((gq < 2) ? (x + (size_t)sN * 64 + gq * 32)
                                                   : (x + (size_t)dN * 64 + (gq - 2) * 32));
        #pragma unroll
        for (int i = 0; i < 8; ++i) rc0[i] = p[i];
    }

    // ---------- one-time weight staging: split + store [n][k] ----------
    for (int i = tid; i < 128 * 232; i += NTHR) {
        const int j = i / 232, k = i - j * 232;
        const float v = (k < K1) ? W1[j * K1 + k] : 0.f;
        const u32 uv = __float_as_uint(v);
        *(u16*)(smem + OFF_W1H + j * STW1 + k * 2) = (u16)(uv >> 16);
        const float r = v - __uint_as_float(uv & 0xFFFF0000u);
        const __nv_bfloat16 rb = __float2bfloat16(r);
        *(u16*)(smem + OFF_W1L + j * STW1 + k * 2) = *(const u16*)&rb;
    }
    for (int i = tid; i < 32 * 136; i += NTHR) {
        const int j = i / 136, k = i - j * 136;
        const float v = (k < 128) ? W2[j * 128 + k] : 0.f;
        const u32 uv = __float_as_uint(v);
        *(u16*)(smem + OFF_W2H + j * STW2 + k * 2) = (u16)(uv >> 16);
        const float r = v - __uint_as_float(uv & 0xFFFF0000u);
        const __nv_bfloat16 rb = __float2bfloat16(r);
        *(u16*)(smem + OFF_W2L + j * STW2 + k * 2) = *(const u16*)&rb;
    }
    if (tid < 128) ((float*)(smem + OFF_B1S))[tid] = b1[tid];
    if (tid < 32)  ((float*)(smem + OFF_B2S))[tid] = b2[tid];
    if (tid < 64)  ((float*)(smem + OFF_W3S))[tid] = W3[tid];
    if (tid < 2)   ((float*)(smem + OFF_B3S))[tid] = b3[tid];

    // ---------- per-lane fragment addresses ----------
    const int mg = wid >> 2;       // m-group: rows mg*32 .. +31
    const int nq = wid & 3;        // n-quarter: layer1 cols nq*32 .. +31; layer2 cols nq*8
    const int aRow = mg * 32 + ((lane >> 3) & 1) * 8 + (lane & 7);
    const u32 aOff = (u32)aRow * STA + (u32)(lane >> 4) * 16;
    const u32 aBH  = sb + OFF_AH + aOff;
    const u32 aBL  = sb + OFF_AL + aOff;
    const int bSel = lane >> 4, bKh = (lane >> 3) & 1, bRow = lane & 7;
    const u32 b1off = (u32)(nq * 32 + bSel * 8 + bRow) * STW1 + (u32)bKh * 16;
    const u32 b1H  = sb + OFF_W1H + b1off;
    const u32 b1L  = sb + OFF_W1L + b1off;
    const u32 b2off = (u32)(nq * 8 + (lane & 7)) * STW2 + (u32)((lane >> 3) & 1) * 16;
    const u32 b2H  = sb + OFF_W2H + b2off;
    const u32 b2L  = sb + OFF_W2L + b2off;

    const float* b1s = (const float*)(smem + OFF_B1S);
    const float* b2s = (const float*)(smem + OFF_B2S);
    const float* W3s = (const float*)(smem + OFF_W3S);
    const float* b3s = (const float*)(smem + OFF_B3S);
    float* h2s = (float*)(smem + OFF_H2);   // [128][34] f32

    __syncthreads();   // weights staged

    for (int tile = blockIdx.x; tile < ntiles; tile += gridDim.x) {
        const int ebase = tile * TILE_E;
        const int  eg   = ebase + gm;
        const size_t egc = ve ? (size_t)eg : 0;

        // ---------- STS chunk0 from prefetched registers ----------
        {
            const float* v = (const float*)rc0;
            const u32 wb = (u32)gm * STA + (u32)gq * 64;
            #pragma unroll
            for (int t8 = 0; t8 < 4; ++t8)
                sts_split8(smem, wb + t8 * 16, v + 8 * t8);
        }

        // ---------- prefetch chunk1 -> registers (covered by chunk0 MMA) ----------
        float4 rc1[8];
        if (gq < 2) {
            const float4* p = (const float4*)(efeat + egc * 64 + gq * 32);
            #pragma unroll
            for (int i = 0; i < 8; ++i) rc1[i] = p[i];
        } else if (gq == 2) {
            float* v = (float*)rc1;
            #pragma unroll
            for (int j = 0; j < 10; ++j) {
                v[j]      = nodef[(size_t)sN * 10 + j];
                v[10 + j] = nodef[(size_t)dN * 10 + j];
            }
            v[20] = edgef[egc * 2];
            v[21] = edgef[egc * 2 + 1];
            #pragma unroll
            for (int j = 22; j < 32; ++j) v[j] = 0.f;
        }
        __syncthreads();

        float acc[2][4][4];
        #pragma unroll
        for (int i = 0; i < 2; ++i)
            #pragma unroll
            for (int j = 0; j < 4; ++j)
                #pragma unroll
                for (int p = 0; p < 4; ++p) acc[i][j][p] = 0.f;

        l1_chunk<8>(acc, aBH, aBL, b1H, b1L, 0);
        __syncthreads();

        // ---------- STS chunk1 from registers ----------
        if (gq < 2) {
            const float* v = (const float*)rc1;
            const u32 wb = (u32)gm * STA + (u32)gq * 64;
            #pragma unroll
            for (int t8 = 0; t8 < 4; ++t8)
                sts_split8(smem, wb + t8 * 16, v + 8 * t8);
        } else if (gq == 2) {
            const float* v = (const float*)rc1;
            const u32 wb = (u32)gm * STA + 128;
            #pragma unroll
            for (int t8 = 0; t8 < 4; ++t8)
                sts_split8(smem, wb + t8 * 16, v + 8 * t8);
        }
        __syncthreads();

        l1_chunk<6>(acc, aBH, aBL, b1H, b1L, 8 * 32);
        __syncthreads();

        // ---------- epilogue 1: bias + relu + split -> h1 into A buffers ----------
        #pragma unroll
        for (int mb = 0; mb < 2; ++mb) {
            const int r0 = mg * 32 + mb * 16 + (lane >> 2);
            #pragma unroll
            for (int nbl = 0; nbl < 4; ++nbl) {
                const int n0 = nq * 32 + nbl * 8 + 2 * (lane & 3);
                const float bb0 = b1s[n0], bb1 = b1s[n0 + 1];
                float f0 = fmaxf(acc[mb][nbl][0] + bb0, 0.f);
                float f1 = fmaxf(acc[mb][nbl][1] + bb1, 0.f);
                u32 hp, lp;
                splitp(f0, f1, hp, lp);
                *(u32*)(smem + OFF_AH + r0 * STA + n0 * 2) = hp;
                *(u32*)(smem + OFF_AL + r0 * STA + n0 * 2) = lp;
                f0 = fmaxf(acc[mb][nbl][2] + bb0, 0.f);
                f1 = fmaxf(acc[mb][nbl][3] + bb1, 0.f);
                splitp(f0, f1, hp, lp);
                *(u32*)(smem + OFF_AH + (r0 + 8) * STA + n0 * 2) = hp;
                *(u32*)(smem + OFF_AL + (r0 + 8) * STA + n0 * 2) = lp;
            }
        }

        // ---------- prefetch next tile: indices + chunk0 (covered by layer2/3) ----------
        {
            const int tn = tile + gridDim.x;
            if (tn < ntiles) {
                const int eg2 = tn * TILE_E + gm;
                ve = eg2 < E;
                sN = ve ? src[eg2] : 0;
                dN = ve ? dst[eg2] : 0;
                const float4* p = (const float4*)((gq < 2) ? (x + (size_t)sN * 64 + gq * 32)
                                                           : (x + (size_t)dN * 64 + (gq - 2) * 32));
                #pragma unroll
                for (int i = 0; i < 8; ++i) rc0[i] = p[i];
            }
        }
        __syncthreads();

        // ---------- layer 2: h1[128x128] @ W2^T -> h2[128x32]; warp owns 32r x 8c ----------
        float acc2[2][4];
        #pragma unroll
        for (int i = 0; i < 2; ++i)
            #pragma unroll
            for (int p = 0; p < 4; ++p) acc2[i][p] = 0.f;

        #pragma unroll
        for (int ks = 0; ks < 8; ++ks) {
            u32 ah[2][4], al[2][4];
            #pragma unroll
            for (int mb = 0; mb < 2; ++mb) {
                ldm4(aBH + mb * (16 * STA) + ks * 32, ah[mb]);
                ldm4(aBL + mb * (16 * STA) + ks * 32, al[mb]);
            }
            u32 bh[2], bl[2];
            ldm2(b2H + ks * 32, bh);
            ldm2(b2L + ks * 32, bl);
            #pragma unroll
            for (int mb = 0; mb < 2; ++mb) {
                mma_bf16(acc2[mb], ah[mb], bh[0], bh[1]);
                mma_bf16(acc2[mb], al[mb], bh[0], bh[1]);
                mma_bf16(acc2[mb], ah[mb], bl[0], bl[1]);
            }
        }

        // ---------- epilogue 2: bias + relu -> h2s ----------
        #pragma unroll
        for (int mb = 0; mb < 2; ++mb) {
            const int r0 = mg * 32 + mb * 16 + (lane >> 2);
            const int c0 = nq * 8 + 2 * (lane & 3);
            const float bb0 = b2s[c0], bb1 = b2s[c0 + 1];
            *(float2*)(h2s + r0 * 34 + c0) =
                make_float2(fmaxf(acc2[mb][0] + bb0, 0.f),
                            fmaxf(acc2[mb][1] + bb1, 0.f));
            *(float2*)(h2s + (r0 + 8) * 34 + c0) =
                make_float2(fmaxf(acc2[mb][2] + bb0, 0.f),
                            fmaxf(acc2[mb][3] + bb1, 0.f));
        }
        __syncthreads();

        // ---------- layer 3: h2[128x32] @ W3^T + b3 -> out ----------
        if (tid < TILE_E * 2) {
            const int row = tid >> 1, cls = tid & 1;
            float sum = b3s[cls];
            #pragma unroll
            for (int k = 0; k < 32; ++k)
                sum = fmaf(h2s[row * 34 + k], W3s[cls * 32 + k], sum);
            const int ego = ebase + row;
            if (ego < E) out[(size_t)ego * 2 + cls] = sum;
        }
        // no trailing barrier: next tile's first smem writes (A buffers) conflict only
        // with layer-2 reads, which complete before the barrier above; h2s is next
        // written 5 barriers into the following iteration.
    }
}

extern "C" void kernel_launch(void* const* d_in, const int* in_sizes, int n_in,
                              void* d_out, int out_size) {
    const float* x     = (const float*)d_in[0];
    const float* efeat = (const float*)d_in[1];
    const float* nodef = (const float*)d_in[2];
    const float* edgef = (const float*)d_in[3];
    const int*   src   = (const int*)d_in[4];
    const int*   dst   = (const int*)d_in[5];
    const float* W1    = (const float*)d_in[6];
    const float* b1    = (const float*)d_in[7];
    const float* W2    = (const float*)d_in[8];
    const float* b2    = (const float*)d_in[9];
    const float* W3    = (const float*)d_in[10];
    const float* b3    = (const float*)d_in[11];
    float* out = (float*)d_out;

    const int E      = in_sizes[4];
    const int ntiles = (E + TILE_E - 1) / TILE_E;

    cudaFuncSetAttribute(edge_mlp_hmma, cudaFuncAttributeMaxDynamicSharedMemorySize, SMEM_SZ);
    int grid = 152;
    if (grid > ntiles) grid = ntiles;
    edge_mlp_hmma<<<grid, NTHR, SMEM_SZ>>>(x, efeat, nodef, edgef, src, dst,
                                           W1, b1, W2, b2, W3, b3, out, E, ntiles);
}

// round 9
// speedup vs baseline: 2.4366x; 1.0126x over previous
#include <cuda_runtime.h>
#include <cuda_bf16.h>
#include <cstdint>

typedef uint32_t u32;
typedef unsigned short u16;

#define NTHR   512
#define TILE_E 128
#define K1     214

#define STA  272      // A/h1 row stride bytes (136 bf16)
#define STW1 464      // W1 row stride (232 bf16)
#define STW2 272

#define OFF_B1S 0
#define OFF_B2S 512
#define OFF_W3S 640
#define OFF_B3S 896
#define OFF_AH  1024
#define OFF_AL  (OFF_AH + 128 * STA)
#define OFF_W1H (OFF_AL + 128 * STA)
#define OFF_W1L (OFF_W1H + 128 * STW1)
#define OFF_W2H (OFF_W1L + 128 * STW1)
#define OFF_W2L (OFF_W2H + 32 * STW2)
#define OFF_H2  (OFF_W2L + 32 * STW2)
#define SMEM_SZ (OFF_H2 + 128 * 136)       // 224256 B

__device__ __forceinline__ u32 s2u(const void* p) {
    u32 a;
    asm("{ .reg .u64 t; cvta.to.shared.u64 t, %1; cvt.u32.u64 %0, t; }" : "=r"(a) : "l"(p));
    return a;
}
__device__ __forceinline__ void ldm4(u32 addr, u32* r) {
    asm volatile("ldmatrix.sync.aligned.m8n8.x4.shared.b16 {%0,%1,%2,%3}, [%4];"
                 : "=r"(r[0]), "=r"(r[1]), "=r"(r[2]), "=r"(r[3]) : "r"(addr));
}
__device__ __forceinline__ void ldm2(u32 addr, u32* r) {
    asm volatile("ldmatrix.sync.aligned.m8n8.x2.shared.b16 {%0,%1}, [%2];"
                 : "=r"(r[0]), "=r"(r[1]) : "r"(addr));
}
__device__ __forceinline__ void mma_bf16(float* c, const u32* a, u32 b0, u32 b1) {
    asm volatile("mma.sync.aligned.m16n8k16.row.col.f32.bf16.bf16.f32 "
                 "{%0,%1,%2,%3}, {%4,%5,%6,%7}, {%8,%9}, {%0,%1,%2,%3};"
                 : "+f"(c[0]), "+f"(c[1]), "+f"(c[2]), "+f"(c[3])
                 : "r"(a[0]), "r"(a[1]), "r"(a[2]), "r"(a[3]), "r"(b0), "r"(b1));
}
// pack two f32 -> bf16x2 in one cvt
__device__ __forceinline__ u32 cvt2(float a, float b) {
    u32 r;
    asm("cvt.rn.bf16x2.f32 %0, %2, %1;" : "=r"(r) : "f"(a), "f"(b));
    return r;
}
// split (a,b) into packed-bf16x2 hi (truncation) + lo (rounded residual)
__device__ __forceinline__ void splitp(float a, float b, u32& hp, u32& lp) {
    u32 ua = __float_as_uint(a), ub = __float_as_uint(b);
    hp = __byte_perm(ua, ub, 0x7632);
    float ra = a - __uint_as_float(ua & 0xFFFF0000u);
    float rb = b - __uint_as_float(ub & 0xFFFF0000u);
    lp = cvt2(ra, rb);
}
// split 8 floats (2 float4) and store 16B hi + 16B lo at offset
__device__ __forceinline__ void sts_split8(char* smem, u32 wb, const float* v) {
    uint4 hv, lv;
    splitp(v[0], v[1], hv.x, lv.x);
    splitp(v[2], v[3], hv.y, lv.y);
    splitp(v[4], v[5], hv.z, lv.z);
    splitp(v[6], v[7], hv.w, lv.w);
    *(uint4*)(smem + OFF_AH + wb) = hv;
    *(uint4*)(smem + OFF_AL + wb) = lv;
}

// layer-1 chunk, term-outer ordering: per k-step load all fragments,
// then batch-issue the 3 split terms (8 independent MMAs per batch).
template <int NKS>
__device__ __forceinline__ void l1_chunk(float (&acc)[2][4][4],
                                         u32 aBH, u32 aBL,
                                         u32 b1H, u32 b1L, u32 bk)
{
    #pragma unroll
    for (int ks = 0; ks < NKS; ++ks) {
        u32 ah[2][4], al[2][4], bh[2][4], bl[2][4];
        #pragma unroll
        for (int mb = 0; mb < 2; ++mb) {
            ldm4(aBH + mb * (16 * STA) + ks * 32, ah[mb]);
            ldm4(aBL + mb * (16 * STA) + ks * 32, al[mb]);
        }
        #pragma unroll
        for (int np = 0; np < 2; ++np) {
            ldm4(b1H + np * (16 * STW1) + bk + ks * 32, bh[np]);
            ldm4(b1L + np * (16 * STW1) + bk + ks * 32, bl[np]);
        }
        // term 1: Ah*Bh (8 independent MMAs)
        #pragma unroll
        for (int np = 0; np < 2; ++np)
            #pragma unroll
            for (int mb = 0; mb < 2; ++mb) {
                mma_bf16(acc[mb][2 * np],     ah[mb], bh[np][0], bh[np][1]);
                mma_bf16(acc[mb][2 * np + 1], ah[mb], bh[np][2], bh[np][3]);
            }
        // term 2: Al*Bh
        #pragma unroll
        for (int np = 0; np < 2; ++np)
            #pragma unroll
            for (int mb = 0; mb < 2; ++mb) {
                mma_bf16(acc[mb][2 * np],     al[mb], bh[np][0], bh[np][1]);
                mma_bf16(acc[mb][2 * np + 1], al[mb], bh[np][2], bh[np][3]);
            }
        // term 3: Ah*Bl
        #pragma unroll
        for (int np = 0; np < 2; ++np)
            #pragma unroll
            for (int mb = 0; mb < 2; ++mb) {
                mma_bf16(acc[mb][2 * np],     ah[mb], bl[np][0], bl[np][1]);
                mma_bf16(acc[mb][2 * np + 1], ah[mb], bl[np][2], bl[np][3]);
            }
    }
}

extern "C" __global__ void __launch_bounds__(NTHR, 1)
edge_mlp_hmma(const float* __restrict__ x, const float* __restrict__ efeat,
              const float* __restrict__ nodef, const float* __restrict__ edgef,
              const int* __restrict__ src, const int* __restrict__ dst,
              const float* __restrict__ W1, const float* __restrict__ b1,
              const float* __restrict__ W2, const float* __restrict__ b2,
              const float* __restrict__ W3, const float* __restrict__ b3,
              float* __restrict__ out, int E, int ntiles)
{
    extern __shared__ char smem[];
    const u32 sb   = s2u(smem);
    const int tid  = threadIdx.x;
    const int wid  = tid >> 5;
    const int lane = tid & 31;

    const int gm = tid >> 2, gq = tid & 3;  // gather: 4 threads per edge

    // ---------- initial prefetch: tile-0 indices + chunk0 into registers ----------
    int sN, dN;
    bool ve;
    float4 rc0[8];
    {
        const int eg = blockIdx.x * TILE_E + gm;
        ve = eg < E;
        sN = ve ? src[eg] : 0;
        dN = ve ? dst[eg] : 0;
        const float4* p = (const float4*)((gq < 2) ? (x + (size_t)sN * 64 + gq * 32)
                                                   : (x + (size_t)dN * 64 + (gq - 2) * 32));
        #pragma unroll
        for (int i = 0; i < 8; ++i) rc0[i] = p[i];
    }

    // ---------- one-time weight staging: split + store [n][k] ----------
    for (int i = tid; i < 128 * 232; i += NTHR) {
        const int j = i / 232, k = i - j * 232;
        const float v = (k < K1) ? W1[j * K1 + k] : 0.f;
        const u32 uv = __float_as_uint(v);
        *(u16*)(smem + OFF_W1H + j * STW1 + k * 2) = (u16)(uv >> 16);
        const float r = v - __uint_as_float(uv & 0xFFFF0000u);
        const __nv_bfloat16 rb = __float2bfloat16(r);
        *(u16*)(smem + OFF_W1L + j * STW1 + k * 2) = *(const u16*)&rb;
    }
    for (int i = tid; i < 32 * 136; i += NTHR) {
        const int j = i / 136, k = i - j * 136;
        const float v = (k < 128) ? W2[j * 128 + k] : 0.f;
        const u32 uv = __float_as_uint(v);
        *(u16*)(smem + OFF_W2H + j * STW2 + k * 2) = (u16)(uv >> 16);
        const float r = v - __uint_as_float(uv & 0xFFFF0000u);
        const __nv_bfloat16 rb = __float2bfloat16(r);
        *(u16*)(smem + OFF_W2L + j * STW2 + k * 2) = *(const u16*)&rb;
    }
    if (tid < 128) ((float*)(smem + OFF_B1S))[tid] = b1[tid];
    if (tid < 32)  ((float*)(smem + OFF_B2S))[tid] = b2[tid];
    if (tid < 64)  ((float*)(smem + OFF_W3S))[tid] = W3[tid];
    if (tid < 2)   ((float*)(smem + OFF_B3S))[tid] = b3[tid];

    // ---------- per-lane fragment addresses ----------
    const int mg = wid >> 2;       // m-group: rows mg*32 .. +31
    const int nq = wid & 3;        // n-quarter: layer1 cols nq*32 .. +31; layer2 cols nq*8
    const int aRow = mg * 32 + ((lane >> 3) & 1) * 8 + (lane & 7);
    const u32 aOff = (u32)aRow * STA + (u32)(lane >> 4) * 16;
    const u32 aBH  = sb + OFF_AH + aOff;
    const u32 aBL  = sb + OFF_AL + aOff;
    const int bSel = lane >> 4, bKh = (lane >> 3) & 1, bRow = lane & 7;
    const u32 b1off = (u32)(nq * 32 + bSel * 8 + bRow) * STW1 + (u32)bKh * 16;
    const u32 b1H  = sb + OFF_W1H + b1off;
    const u32 b1L  = sb + OFF_W1L + b1off;
    const u32 b2off = (u32)(nq * 8 + (lane & 7)) * STW2 + (u32)((lane >> 3) & 1) * 16;
    const u32 b2H  = sb + OFF_W2H + b2off;
    const u32 b2L  = sb + OFF_W2L + b2off;

    const float* b1s = (const float*)(smem + OFF_B1S);
    const float* b2s = (const float*)(smem + OFF_B2S);
    const float* W3s = (const float*)(smem + OFF_W3S);
    const float* b3s = (const float*)(smem + OFF_B3S);
    float* h2s = (float*)(smem + OFF_H2);   // [128][34] f32

    __syncthreads();   // weights staged

    for (int tile = blockIdx.x; tile < ntiles; tile += gridDim.x) {
        const int ebase = tile * TILE_E;
        const int  eg   = ebase + gm;
        const size_t egc = ve ? (size_t)eg : 0;

        // ---------- STS chunk0 from prefetched registers ----------
        {
            const float* v = (const float*)rc0;
            const u32 wb = (u32)gm * STA + (u32)gq * 64;
            #pragma unroll
            for (int t8 = 0; t8 < 4; ++t8)
                sts_split8(smem, wb + t8 * 16, v + 8 * t8);
        }

        // ---------- prefetch chunk1 -> registers (covered by chunk0 MMA) ----------
        float4 rc1[8];
        if (gq < 2) {
            const float4* p = (const float4*)(efeat + egc * 64 + gq * 32);
            #pragma unroll
            for (int i = 0; i < 8; ++i) rc1[i] = p[i];
        } else if (gq == 2) {
            float* v = (float*)rc1;
            #pragma unroll
            for (int j = 0; j < 10; ++j) {
                v[j]      = nodef[(size_t)sN * 10 + j];
                v[10 + j] = nodef[(size_t)dN * 10 + j];
            }
            v[20] = edgef[egc * 2];
            v[21] = edgef[egc * 2 + 1];
            #pragma unroll
            for (int j = 22; j < 32; ++j) v[j] = 0.f;
        }
        __syncthreads();

        float acc[2][4][4];
        #pragma unroll
        for (int i = 0; i < 2; ++i)
            #pragma unroll
            for (int j = 0; j < 4; ++j)
                #pragma unroll
                for (int p = 0; p < 4; ++p) acc[i][j][p] = 0.f;

        l1_chunk<8>(acc, aBH, aBL, b1H, b1L, 0);
        __syncthreads();

        // ---------- STS chunk1 from registers ----------
        if (gq < 2) {
            const float* v = (const float*)rc1;
            const u32 wb = (u32)gm * STA + (u32)gq * 64;
            #pragma unroll
            for (int t8 = 0; t8 < 4; ++t8)
                sts_split8(smem, wb + t8 * 16, v + 8 * t8);
        } else if (gq == 2) {
            const float* v = (const float*)rc1;
            const u32 wb = (u32)gm * STA + 128;
            #pragma unroll
            for (int t8 = 0; t8 < 4; ++t8)
                sts_split8(smem, wb + t8 * 16, v + 8 * t8);
        }
        __syncthreads();

        l1_chunk<6>(acc, aBH, aBL, b1H, b1L, 8 * 32);
        __syncthreads();

        // ---------- epilogue 1: bias + relu + split -> h1 into A buffers ----------
        #pragma unroll
        for (int mb = 0; mb < 2; ++mb) {
            const int r0 = mg * 32 + mb * 16 + (lane >> 2);
            #pragma unroll
            for (int nbl = 0; nbl < 4; ++nbl) {
                const int n0 = nq * 32 + nbl * 8 + 2 * (lane & 3);
                const float bb0 = b1s[n0], bb1 = b1s[n0 + 1];
                float f0 = fmaxf(acc[mb][nbl][0] + bb0, 0.f);
                float f1 = fmaxf(acc[mb][nbl][1] + bb1, 0.f);
                u32 hp, lp;
                splitp(f0, f1, hp, lp);
                *(u32*)(smem + OFF_AH + r0 * STA + n0 * 2) = hp;
                *(u32*)(smem + OFF_AL + r0 * STA + n0 * 2) = lp;
                f0 = fmaxf(acc[mb][nbl][2] + bb0, 0.f);
                f1 = fmaxf(acc[mb][nbl][3] + bb1, 0.f);
                splitp(f0, f1, hp, lp);
                *(u32*)(smem + OFF_AH + (r0 + 8) * STA + n0 * 2) = hp;
                *(u32*)(smem + OFF_AL + (r0 + 8) * STA + n0 * 2) = lp;
            }
        }

        // ---------- prefetch next tile: indices + chunk0 (covered by layer2/3) ----------
        {
            const int tn = tile + gridDim.x;
            if (tn < ntiles) {
                const int eg2 = tn * TILE_E + gm;
                ve = eg2 < E;
                sN = ve ? src[eg2] : 0;
                dN = ve ? dst[eg2] : 0;
                const float4* p = (const float4*)((gq < 2) ? (x + (size_t)sN * 64 + gq * 32)
                                                           : (x + (size_t)dN * 64 + (gq - 2) * 32));
                #pragma unroll
                for (int i = 0; i < 8; ++i) rc0[i] = p[i];
            }
        }
        __syncthreads();

        // ---------- layer 2: h1[128x128] @ W2^T -> h2[128x32]; warp owns 32r x 8c ----------
        float acc2[2][4], acc2c[2][4];
        #pragma unroll
        for (int i = 0; i < 2; ++i)
            #pragma unroll
            for (int p = 0; p < 4; ++p) { acc2[i][p] = 0.f; acc2c[i][p] = 0.f; }

        #pragma unroll
        for (int ks = 0; ks < 8; ++ks) {
            u32 ah[2][4], al[2][4], bh[2], bl[2];
            #pragma unroll
            for (int mb = 0; mb < 2; ++mb) {
                ldm4(aBH + mb * (16 * STA) + ks * 32, ah[mb]);
                ldm4(aBL + mb * (16 * STA) + ks * 32, al[mb]);
            }
            ldm2(b2H + ks * 32, bh);
            ldm2(b2L + ks * 32, bl);
            // hi*hi into acc2; corrections into acc2c (independent chains)
            #pragma unroll
            for (int mb = 0; mb < 2; ++mb) mma_bf16(acc2[mb],  ah[mb], bh[0], bh[1]);
            #pragma unroll
            for (int mb = 0; mb < 2; ++mb) mma_bf16(acc2c[mb], al[mb], bh[0], bh[1]);
            #pragma unroll
            for (int mb = 0; mb < 2; ++mb) mma_bf16(acc2c[mb], ah[mb], bl[0], bl[1]);
        }

        // ---------- epilogue 2: bias + relu -> h2s ----------
        #pragma unroll
        for (int mb = 0; mb < 2; ++mb) {
            const int r0 = mg * 32 + mb * 16 + (lane >> 2);
            const int c0 = nq * 8 + 2 * (lane & 3);
            const float bb0 = b2s[c0], bb1 = b2s[c0 + 1];
            *(float2*)(h2s + r0 * 34 + c0) =
                make_float2(fmaxf(acc2[mb][0] + acc2c[mb][0] + bb0, 0.f),
                            fmaxf(acc2[mb][1] + acc2c[mb][1] + bb1, 0.f));
            *(float2*)(h2s + (r0 + 8) * 34 + c0) =
                make_float2(fmaxf(acc2[mb][2] + acc2c[mb][2] + bb0, 0.f),
                            fmaxf(acc2[mb][3] + acc2c[mb][3] + bb1, 0.f));
        }
        __syncthreads();

        // ---------- layer 3: h2[128x32] @ W3^T + b3 -> out ----------
        if (tid < TILE_E * 2) {
            const int row = tid >> 1, cls = tid & 1;
            float sum = b3s[cls];
            #pragma unroll
            for (int k = 0; k < 32; ++k)
                sum = fmaf(h2s[row * 34 + k], W3s[cls * 32 + k], sum);
            const int ego = ebase + row;
            if (ego < E) out[(size_t)ego * 2 + cls] = sum;
        }
        // no trailing barrier (safe: see round-8 analysis)
    }
}

extern "C" void kernel_launch(void* const* d_in, const int* in_sizes, int n_in,
                              void* d_out, int out_size) {
    const float* x     = (const float*)d_in[0];
    const float* efeat = (const float*)d_in[1];
    const float* nodef = (const float*)d_in[2];
    const float* edgef = (const float*)d_in[3];
    const int*   src   = (const int*)d_in[4];
    const int*   dst   = (const int*)d_in[5];
    const float* W1    = (const float*)d_in[6];
    const float* b1    = (const float*)d_in[7];
    const float* W2    = (const float*)d_in[8];
    const float* b2    = (const float*)d_in[9];
    const float* W3    = (const float*)d_in[10];
    const float* b3    = (const float*)d_in[11];
    float* out = (float*)d_out;

    const int E      = in_sizes[4];
    const int ntiles = (E + TILE_E - 1) / TILE_E;

    cudaFuncSetAttribute(edge_mlp_hmma, cudaFuncAttributeMaxDynamicSharedMemorySize, SMEM_SZ);
    int grid = 152;
    if (grid > ntiles) grid = ntiles;
    edge_mlp_hmma<<<grid, NTHR, SMEM_SZ>>>(x, efeat, nodef, edgef, src, dst,
                                           W1, b1, W2, b2, W3, b3, out, E, ntiles);
}

// round 10
// speedup vs baseline: 2.6386x; 1.0829x over previous
#include <cuda_runtime.h>
#include <cuda_bf16.h>
#include <cstdint>

typedef uint32_t u32;
typedef unsigned short u16;

#define NTHR   512
#define TILE_E 64          // per group
#define K1     214

#define STA  272           // A/h1 row stride bytes (136 bf16)
#define STW1 464           // W1 row stride (232 bf16)
#define STW2 272

#define A_PART   17408     // 64 rows * STA
#define OFF_B1S  0
#define OFF_B2S  512
#define OFF_W3S  640
#define OFF_B3S  896
#define OFF_A0   1024      // group g A: hi at OFF_A0+g*2*A_PART, lo at +A_PART
#define OFF_W1H  (OFF_A0 + 4 * A_PART)          // 70656
#define OFF_W1L  (OFF_W1H + 128 * STW1)         // 130048
#define OFF_W2H  (OFF_W1L + 128 * STW1)         // 189440
#define OFF_W2L  (OFF_W2H + 32 * STW2)          // 198144
#define OFF_H2   (OFF_W2L + 32 * STW2)          // 206848; per group +8704
#define SMEM_SZ  (OFF_H2 + 2 * 64 * 34 * 4)     // 224256 B

__device__ __forceinline__ u32 s2u(const void* p) {
    u32 a;
    asm("{ .reg .u64 t; cvta.to.shared.u64 t, %1; cvt.u32.u64 %0, t; }" : "=r"(a) : "l"(p));
    return a;
}
__device__ __forceinline__ void ldm4(u32 addr, u32* r) {
    asm volatile("ldmatrix.sync.aligned.m8n8.x4.shared.b16 {%0,%1,%2,%3}, [%4];"
                 : "=r"(r[0]), "=r"(r[1]), "=r"(r[2]), "=r"(r[3]) : "r"(addr));
}
__device__ __forceinline__ void ldm2(u32 addr, u32* r) {
    asm volatile("ldmatrix.sync.aligned.m8n8.x2.shared.b16 {%0,%1}, [%2];"
                 : "=r"(r[0]), "=r"(r[1]) : "r"(addr));
}
__device__ __forceinline__ void mma_bf16(float* c, const u32* a, u32 b0, u32 b1) {
    asm volatile("mma.sync.aligned.m16n8k16.row.col.f32.bf16.bf16.f32 "
                 "{%0,%1,%2,%3}, {%4,%5,%6,%7}, {%8,%9}, {%0,%1,%2,%3};"
                 : "+f"(c[0]), "+f"(c[1]), "+f"(c[2]), "+f"(c[3])
                 : "r"(a[0]), "r"(a[1]), "r"(a[2]), "r"(a[3]), "r"(b0), "r"(b1));
}
__device__ __forceinline__ u32 cvt2(float a, float b) {
    u32 r;
    asm("cvt.rn.bf16x2.f32 %0, %2, %1;" : "=r"(r) : "f"(a), "f"(b));
    return r;
}
__device__ __forceinline__ void splitp(float a, float b, u32& hp, u32& lp) {
    u32 ua = __float_as_uint(a), ub = __float_as_uint(b);
    hp = __byte_perm(ua, ub, 0x7632);
    float ra = a - __uint_as_float(ua & 0xFFFF0000u);
    float rb = b - __uint_as_float(ub & 0xFFFF0000u);
    lp = cvt2(ra, rb);
}
// split 8 floats and store 16B hi at base+wb, 16B lo at base+A_PART+wb
__device__ __forceinline__ void sts_split8(char* smem, u32 base, u32 wb, const float* v) {
    uint4 hv, lv;
    splitp(v[0], v[1], hv.x, lv.x);
    splitp(v[2], v[3], hv.y, lv.y);
    splitp(v[4], v[5], hv.z, lv.z);
    splitp(v[6], v[7], hv.w, lv.w);
    *(uint4*)(smem + base + wb) = hv;
    *(uint4*)(smem + base + A_PART + wb) = lv;
}

// layer-1 chunk, term-outer ordering
template <int NKS>
__device__ __forceinline__ void l1_chunk(float (&acc)[2][4][4],
                                         u32 aBH, u32 aBL,
                                         u32 b1H, u32 b1L, u32 bk)
{
    #pragma unroll
    for (int ks = 0; ks < NKS; ++ks) {
        u32 ah[2][4], al[2][4], bh[2][4], bl[2][4];
        #pragma unroll
        for (int mb = 0; mb < 2; ++mb) {
            ldm4(aBH + mb * (16 * STA) + ks * 32, ah[mb]);
            ldm4(aBL + mb * (16 * STA) + ks * 32, al[mb]);
        }
        #pragma unroll
        for (int np = 0; np < 2; ++np) {
            ldm4(b1H + np * (16 * STW1) + bk + ks * 32, bh[np]);
            ldm4(b1L + np * (16 * STW1) + bk + ks * 32, bl[np]);
        }
        #pragma unroll
        for (int np = 0; np < 2; ++np)
            #pragma unroll
            for (int mb = 0; mb < 2; ++mb) {
                mma_bf16(acc[mb][2 * np],     ah[mb], bh[np][0], bh[np][1]);
                mma_bf16(acc[mb][2 * np + 1], ah[mb], bh[np][2], bh[np][3]);
            }
        #pragma unroll
        for (int np = 0; np < 2; ++np)
            #pragma unroll
            for (int mb = 0; mb < 2; ++mb) {
                mma_bf16(acc[mb][2 * np],     al[mb], bh[np][0], bh[np][1]);
                mma_bf16(acc[mb][2 * np + 1], al[mb], bh[np][2], bh[np][3]);
            }
        #pragma unroll
        for (int np = 0; np < 2; ++np)
            #pragma unroll
            for (int mb = 0; mb < 2; ++mb) {
                mma_bf16(acc[mb][2 * np],     ah[mb], bl[np][0], bl[np][1]);
                mma_bf16(acc[mb][2 * np + 1], ah[mb], bl[np][2], bl[np][3]);
            }
    }
}

extern "C" __global__ void __launch_bounds__(NTHR, 1)
edge_mlp_hmma(const float* __restrict__ x, const float* __restrict__ efeat,
              const float* __restrict__ nodef, const float* __restrict__ edgef,
              const int* __restrict__ src, const int* __restrict__ dst,
              const float* __restrict__ W1, const float* __restrict__ b1,
              const float* __restrict__ W2, const float* __restrict__ b2,
              const float* __restrict__ W3, const float* __restrict__ b3,
              float* __restrict__ out, int E, int ntiles)
{
    extern __shared__ char smem[];
    const u32 sb   = s2u(smem);
    const int tid  = threadIdx.x;
    const int g    = tid >> 8;          // pipeline group 0/1
    const int gt   = tid & 255;         // thread within group
    const int wg   = gt >> 5;           // warp within group (0..7)
    const int lane = tid & 31;
    const int barid = g + 1;            // named barrier id for this group

    const u32 aBase = OFF_A0 + (u32)g * (2 * A_PART);   // hi base; lo = +A_PART

    const int gm = gt >> 2, gq = gt & 3;  // gather: 4 threads per edge (64 edges)

    // ---------- initial prefetch: this group's tile-0 chunk0 ----------
    int sN, dN;
    bool ve;
    float4 rc0[8];
    {
        const int eg = (blockIdx.x * 2 + g) * TILE_E + gm;
        ve = eg < E;
        sN = ve ? src[eg] : 0;
        dN = ve ? dst[eg] : 0;
        const float4* p = (const float4*)((gq < 2) ? (x + (size_t)sN * 64 + gq * 32)
                                                   : (x + (size_t)dN * 64 + (gq - 2) * 32));
        #pragma unroll
        for (int i = 0; i < 8; ++i) rc0[i] = p[i];
    }

    // ---------- one-time weight staging (whole block) ----------
    for (int i = tid; i < 128 * 232; i += NTHR) {
        const int j = i / 232, k = i - j * 232;
        const float v = (k < K1) ? W1[j * K1 + k] : 0.f;
        const u32 uv = __float_as_uint(v);
        *(u16*)(smem + OFF_W1H + j * STW1 + k * 2) = (u16)(uv >> 16);
        const float r = v - __uint_as_float(uv & 0xFFFF0000u);
        const __nv_bfloat16 rb = __float2bfloat16(r);
        *(u16*)(smem + OFF_W1L + j * STW1 + k * 2) = *(const u16*)&rb;
    }
    for (int i = tid; i < 32 * 136; i += NTHR) {
        const int j = i / 136, k = i - j * 136;
        const float v = (k < 128) ? W2[j * 128 + k] : 0.f;
        const u32 uv = __float_as_uint(v);
        *(u16*)(smem + OFF_W2H + j * STW2 + k * 2) = (u16)(uv >> 16);
        const float r = v - __uint_as_float(uv & 0xFFFF0000u);
        const __nv_bfloat16 rb = __float2bfloat16(r);
        *(u16*)(smem + OFF_W2L + j * STW2 + k * 2) = *(const u16*)&rb;
    }
    if (tid < 128) ((float*)(smem + OFF_B1S))[tid] = b1[tid];
    if (tid < 32)  ((float*)(smem + OFF_B2S))[tid] = b2[tid];
    if (tid < 64)  ((float*)(smem + OFF_W3S))[tid] = W3[tid];
    if (tid < 2)   ((float*)(smem + OFF_B3S))[tid] = b3[tid];

    // ---------- per-lane fragment addresses (group-local) ----------
    const int mg = wg >> 2;       // m-half: rows mg*32 .. +31 of this group's 64
    const int nq = wg & 3;        // n-quarter
    const int aRow = mg * 32 + ((lane >> 3) & 1) * 8 + (lane & 7);
    const u32 aOff = (u32)aRow * STA + (u32)(lane >> 4) * 16;
    const u32 aBH  = sb + aBase + aOff;
    const u32 aBL  = aBH + A_PART;
    const int bSel = lane >> 4, bKh = (lane >> 3) & 1, bRow = lane & 7;
    const u32 b1off = (u32)(nq * 32 + bSel * 8 + bRow) * STW1 + (u32)bKh * 16;
    const u32 b1H  = sb + OFF_W1H + b1off;
    const u32 b1L  = sb + OFF_W1L + b1off;
    const u32 b2off = (u32)(nq * 8 + (lane & 7)) * STW2 + (u32)((lane >> 3) & 1) * 16;
    const u32 b2H  = sb + OFF_W2H + b2off;
    const u32 b2L  = sb + OFF_W2L + b2off;

    const float* b1s = (const float*)(smem + OFF_B1S);
    const float* b2s = (const float*)(smem + OFF_B2S);
    const float* W3s = (const float*)(smem + OFF_W3S);
    const float* b3s = (const float*)(smem + OFF_B3S);
    float* h2s = (float*)(smem + OFF_H2 + g * 8704);   // [64][34] f32

    __syncthreads();   // weights staged (block-wide, once)

    #define GBAR() asm volatile("bar.sync %0, %1;" :: "r"(barid), "n"(256) : "memory")

    for (int tile = blockIdx.x * 2 + g; tile < ntiles; tile += gridDim.x * 2) {
        const int ebase = tile * TILE_E;
        const int  eg   = ebase + gm;
        const size_t egc = ve ? (size_t)eg : 0;

        // ---------- STS chunk0 from prefetched registers ----------
        {
            const float* v = (const float*)rc0;
            const u32 wb = (u32)gm * STA + (u32)gq * 64;
            #pragma unroll
            for (int t8 = 0; t8 < 4; ++t8)
                sts_split8(smem, aBase, wb + t8 * 16, v + 8 * t8);
        }

        // ---------- prefetch chunk1 -> registers ----------
        float4 rc1[8];
        if (gq < 2) {
            const float4* p = (const float4*)(efeat + egc * 64 + gq * 32);
            #pragma unroll
            for (int i = 0; i < 8; ++i) rc1[i] = p[i];
        } else if (gq == 2) {
            float* v = (float*)rc1;
            #pragma unroll
            for (int j = 0; j < 10; ++j) {
                v[j]      = nodef[(size_t)sN * 10 + j];
                v[10 + j] = nodef[(size_t)dN * 10 + j];
            }
            v[20] = edgef[egc * 2];
            v[21] = edgef[egc * 2 + 1];
            #pragma unroll
            for (int j = 22; j < 32; ++j) v[j] = 0.f;
        }
        GBAR();

        float acc[2][4][4];
        #pragma unroll
        for (int i = 0; i < 2; ++i)
            #pragma unroll
            for (int j = 0; j < 4; ++j)
                #pragma unroll
                for (int p = 0; p < 4; ++p) acc[i][j][p] = 0.f;

        l1_chunk<8>(acc, aBH, aBL, b1H, b1L, 0);
        GBAR();

        // ---------- STS chunk1 ----------
        if (gq < 2) {
            const float* v = (const float*)rc1;
            const u32 wb = (u32)gm * STA + (u32)gq * 64;
            #pragma unroll
            for (int t8 = 0; t8 < 4; ++t8)
                sts_split8(smem, aBase, wb + t8 * 16, v + 8 * t8);
        } else if (gq == 2) {
            const float* v = (const float*)rc1;
            const u32 wb = (u32)gm * STA + 128;
            #pragma unroll
            for (int t8 = 0; t8 < 4; ++t8)
                sts_split8(smem, aBase, wb + t8 * 16, v + 8 * t8);
        }
        GBAR();

        l1_chunk<6>(acc, aBH, aBL, b1H, b1L, 8 * 32);
        GBAR();

        // ---------- epilogue 1: bias + relu + split -> h1 into A buffers ----------
        #pragma unroll
        for (int mb = 0; mb < 2; ++mb) {
            const int r0 = mg * 32 + mb * 16 + (lane >> 2);
            #pragma unroll
            for (int nbl = 0; nbl < 4; ++nbl) {
                const int n0 = nq * 32 + nbl * 8 + 2 * (lane & 3);
                const float bb0 = b1s[n0], bb1 = b1s[n0 + 1];
                float f0 = fmaxf(acc[mb][nbl][0] + bb0, 0.f);
                float f1 = fmaxf(acc[mb][nbl][1] + bb1, 0.f);
                u32 hp, lp;
                splitp(f0, f1, hp, lp);
                *(u32*)(smem + aBase + r0 * STA + n0 * 2) = hp;
                *(u32*)(smem + aBase + A_PART + r0 * STA + n0 * 2) = lp;
                f0 = fmaxf(acc[mb][nbl][2] + bb0, 0.f);
                f1 = fmaxf(acc[mb][nbl][3] + bb1, 0.f);
                splitp(f0, f1, hp, lp);
                *(u32*)(smem + aBase + (r0 + 8) * STA + n0 * 2) = hp;
                *(u32*)(smem + aBase + A_PART + (r0 + 8) * STA + n0 * 2) = lp;
            }
        }

        // ---------- prefetch next tile's chunk0 ----------
        {
            const int tn = tile + gridDim.x * 2;
            if (tn < ntiles) {
                const int eg2 = tn * TILE_E + gm;
                ve = eg2 < E;
                sN = ve ? src[eg2] : 0;
                dN = ve ? dst[eg2] : 0;
                const float4* p = (const float4*)((gq < 2) ? (x + (size_t)sN * 64 + gq * 32)
                                                           : (x + (size_t)dN * 64 + (gq - 2) * 32));
                #pragma unroll
                for (int i = 0; i < 8; ++i) rc0[i] = p[i];
            }
        }
        GBAR();

        // ---------- layer 2: h1[64x128] @ W2^T -> h2[64x32]; warp owns 32r x 8c ----------
        float acc2[2][4], acc2c[2][4];
        #pragma unroll
        for (int i = 0; i < 2; ++i)
            #pragma unroll
            for (int p = 0; p < 4; ++p) { acc2[i][p] = 0.f; acc2c[i][p] = 0.f; }

        #pragma unroll
        for (int ks = 0; ks < 8; ++ks) {
            u32 ah[2][4], al[2][4], bh[2], bl[2];
            #pragma unroll
            for (int mb = 0; mb < 2; ++mb) {
                ldm4(aBH + mb * (16 * STA) + ks * 32, ah[mb]);
                ldm4(aBL + mb * (16 * STA) + ks * 32, al[mb]);
            }
            ldm2(b2H + ks * 32, bh);
            ldm2(b2L + ks * 32, bl);
            #pragma unroll
            for (int mb = 0; mb < 2; ++mb) mma_bf16(acc2[mb],  ah[mb], bh[0], bh[1]);
            #pragma unroll
            for (int mb = 0; mb < 2; ++mb) mma_bf16(acc2c[mb], al[mb], bh[0], bh[1]);
            #pragma unroll
            for (int mb = 0; mb < 2; ++mb) mma_bf16(acc2c[mb], ah[mb], bl[0], bl[1]);
        }

        // ---------- epilogue 2: bias + relu -> h2s ----------
        #pragma unroll
        for (int mb = 0; mb < 2; ++mb) {
            const int r0 = mg * 32 + mb * 16 + (lane >> 2);
            const int c0 = nq * 8 + 2 * (lane & 3);
            const float bb0 = b2s[c0], bb1 = b2s[c0 + 1];
            *(float2*)(h2s + r0 * 34 + c0) =
                make_float2(fmaxf(acc2[mb][0] + acc2c[mb][0] + bb0, 0.f),
                            fmaxf(acc2[mb][1] + acc2c[mb][1] + bb1, 0.f));
            *(float2*)(h2s + (r0 + 8) * 34 + c0) =
                make_float2(fmaxf(acc2[mb][2] + acc2c[mb][2] + bb0, 0.f),
                            fmaxf(acc2[mb][3] + acc2c[mb][3] + bb1, 0.f));
        }
        GBAR();

        // ---------- layer 3: h2[64x32] @ W3^T + b3 -> out ----------
        if (gt < TILE_E * 2) {
            const int row = gt >> 1, cls = gt & 1;
            float sum = b3s[cls];
            #pragma unroll
            for (int k = 0; k < 32; ++k)
                sum = fmaf(h2s[row * 34 + k], W3s[cls * 32 + k], sum);
            const int ego = ebase + row;
            if (ego < E) out[(size_t)ego * 2 + cls] = sum;
        }
        // no trailing barrier: next iteration's A STS conflicts only with layer-2
        // reads, which complete before the barrier above; h2s is rewritten only
        // after the next epilogue-2 (separated by multiple group barriers).
    }
    #undef GBAR
}

extern "C" void kernel_launch(void* const* d_in, const int* in_sizes, int n_in,
                              void* d_out, int out_size) {
    const float* x     = (const float*)d_in[0];
    const float* efeat = (const float*)d_in[1];
    const float* nodef = (const float*)d_in[2];
    const float* edgef = (const float*)d_in[3];
    const int*   src   = (const int*)d_in[4];
    const int*   dst   = (const int*)d_in[5];
    const float* W1    = (const float*)d_in[6];
    const float* b1    = (const float*)d_in[7];
    const float* W2    = (const float*)d_in[8];
    const float* b2    = (const float*)d_in[9];
    const float* W3    = (const float*)d_in[10];
    const float* b3    = (const float*)d_in[11];
    float* out = (float*)d_out;

    const int E      = in_sizes[4];
    const int ntiles = (E + TILE_E - 1) / TILE_E;

    cudaFuncSetAttribute(edge_mlp_hmma, cudaFuncAttributeMaxDynamicSharedMemorySize, SMEM_SZ);
    int grid = 152;
    const int need = (ntiles + 1) / 2;
    if (grid > need) grid = need;
    edge_mlp_hmma<<<grid, NTHR, SMEM_SZ>>>(x, efeat, nodef, edgef, src, dst,
                                           W1, b1, W2, b2, W3, b3, out, E, ntiles);
}

// round 11
// speedup vs baseline: 3.2177x; 1.2195x over previous
#include <cuda_runtime.h>
#include <cuda_bf16.h>
#include <cstdint>

typedef uint32_t u32;
typedef unsigned short u16;

#define NTHR   512
#define TILE_E 32          // per group (4 groups)
#define K1     214

#define STA  272           // A/h1 row stride bytes (136 bf16)
#define STW1 464           // W1 row stride (232 bf16)
#define STW2 272

#define A_PART   8704      // 32 rows * STA
#define OFF_B1S  0
#define OFF_B2S  512
#define OFF_W3S  640
#define OFF_B3S  896
#define OFF_A0   1024      // group g A: hi at OFF_A0+g*2*A_PART, lo at +A_PART
#define OFF_W1H  (OFF_A0 + 8 * A_PART)          // 70656
#define OFF_W1L  (OFF_W1H + 128 * STW1)         // 130048
#define OFF_W2H  (OFF_W1L + 128 * STW1)         // 189440
#define OFF_W2L  (OFF_W2H + 32 * STW2)          // 198144
#define OFF_H2   (OFF_W2L + 32 * STW2)          // 206848; per group +4352
#define SMEM_SZ  (OFF_H2 + 4 * 32 * 34 * 4)     // 224256 B

__device__ __forceinline__ u32 s2u(const void* p) {
    u32 a;
    asm("{ .reg .u64 t; cvta.to.shared.u64 t, %1; cvt.u32.u64 %0, t; }" : "=r"(a) : "l"(p));
    return a;
}
__device__ __forceinline__ void ldm4(u32 addr, u32* r) {
    asm volatile("ldmatrix.sync.aligned.m8n8.x4.shared.b16 {%0,%1,%2,%3}, [%4];"
                 : "=r"(r[0]), "=r"(r[1]), "=r"(r[2]), "=r"(r[3]) : "r"(addr));
}
__device__ __forceinline__ void ldm2(u32 addr, u32* r) {
    asm volatile("ldmatrix.sync.aligned.m8n8.x2.shared.b16 {%0,%1}, [%2];"
                 : "=r"(r[0]), "=r"(r[1]) : "r"(addr));
}
__device__ __forceinline__ void mma_bf16(float* c, const u32* a, u32 b0, u32 b1) {
    asm volatile("mma.sync.aligned.m16n8k16.row.col.f32.bf16.bf16.f32 "
                 "{%0,%1,%2,%3}, {%4,%5,%6,%7}, {%8,%9}, {%0,%1,%2,%3};"
                 : "+f"(c[0]), "+f"(c[1]), "+f"(c[2]), "+f"(c[3])
                 : "r"(a[0]), "r"(a[1]), "r"(a[2]), "r"(a[3]), "r"(b0), "r"(b1));
}
__device__ __forceinline__ u32 cvt2(float a, float b) {
    u32 r;
    asm("cvt.rn.bf16x2.f32 %0, %2, %1;" : "=r"(r) : "f"(a), "f"(b));
    return r;
}
__device__ __forceinline__ void splitp(float a, float b, u32& hp, u32& lp) {
    u32 ua = __float_as_uint(a), ub = __float_as_uint(b);
    hp = __byte_perm(ua, ub, 0x7632);
    float ra = a - __uint_as_float(ua & 0xFFFF0000u);
    float rb = b - __uint_as_float(ub & 0xFFFF0000u);
    lp = cvt2(ra, rb);
}
// split 8 floats and store 16B hi at base+wb, 16B lo at base+A_PART+wb
__device__ __forceinline__ void sts_split8(char* smem, u32 base, u32 wb, const float* v) {
    uint4 hv, lv;
    splitp(v[0], v[1], hv.x, lv.x);
    splitp(v[2], v[3], hv.y, lv.y);
    splitp(v[4], v[5], hv.z, lv.z);
    splitp(v[6], v[7], hv.w, lv.w);
    *(uint4*)(smem + base + wb) = hv;
    *(uint4*)(smem + base + A_PART + wb) = lv;
}

// layer-1 chunk, term-outer ordering; warp tile 32 rows x 32 cols
template <int NKS>
__device__ __forceinline__ void l1_chunk(float (&acc)[2][4][4],
                                         u32 aBH, u32 aBL,
                                         u32 b1H, u32 b1L, u32 bk)
{
    #pragma unroll
    for (int ks = 0; ks < NKS; ++ks) {
        u32 ah[2][4], al[2][4], bh[2][4], bl[2][4];
        #pragma unroll
        for (int mb = 0; mb < 2; ++mb) {
            ldm4(aBH + mb * (16 * STA) + ks * 32, ah[mb]);
            ldm4(aBL + mb * (16 * STA) + ks * 32, al[mb]);
        }
        #pragma unroll
        for (int np = 0; np < 2; ++np) {
            ldm4(b1H + np * (16 * STW1) + bk + ks * 32, bh[np]);
            ldm4(b1L + np * (16 * STW1) + bk + ks * 32, bl[np]);
        }
        #pragma unroll
        for (int np = 0; np < 2; ++np)
            #pragma unroll
            for (int mb = 0; mb < 2; ++mb) {
                mma_bf16(acc[mb][2 * np],     ah[mb], bh[np][0], bh[np][1]);
                mma_bf16(acc[mb][2 * np + 1], ah[mb], bh[np][2], bh[np][3]);
            }
        #pragma unroll
        for (int np = 0; np < 2; ++np)
            #pragma unroll
            for (int mb = 0; mb < 2; ++mb) {
                mma_bf16(acc[mb][2 * np],     al[mb], bh[np][0], bh[np][1]);
                mma_bf16(acc[mb][2 * np + 1], al[mb], bh[np][2], bh[np][3]);
            }
        #pragma unroll
        for (int np = 0; np < 2; ++np)
            #pragma unroll
            for (int mb = 0; mb < 2; ++mb) {
                mma_bf16(acc[mb][2 * np],     ah[mb], bl[np][0], bl[np][1]);
                mma_bf16(acc[mb][2 * np + 1], ah[mb], bl[np][2], bl[np][3]);
            }
    }
}

extern "C" __global__ void __launch_bounds__(NTHR, 1)
edge_mlp_hmma(const float* __restrict__ x, const float* __restrict__ efeat,
              const float* __restrict__ nodef, const float* __restrict__ edgef,
              const int* __restrict__ src, const int* __restrict__ dst,
              const float* __restrict__ W1, const float* __restrict__ b1,
              const float* __restrict__ W2, const float* __restrict__ b2,
              const float* __restrict__ W3, const float* __restrict__ b3,
              float* __restrict__ out, int E, int ntiles)
{
    extern __shared__ char smem[];
    const u32 sb   = s2u(smem);
    const int tid  = threadIdx.x;
    const int g    = tid >> 7;          // pipeline group 0..3
    const int gt   = tid & 127;         // thread within group
    const int wg   = gt >> 5;           // warp within group (0..3)
    const int lane = tid & 31;
    const int barid = g + 1;            // named barrier id for this group

    const u32 aBase = OFF_A0 + (u32)g * (2 * A_PART);   // hi base; lo = +A_PART

    const int gm = gt >> 2, gq = gt & 3;  // gather: 4 threads per edge (32 edges)

    // ---------- initial prefetch: this group's tile-0 chunk0 ----------
    int sN, dN;
    bool ve;
    float4 rc0[8];
    {
        const int eg = (blockIdx.x * 4 + g) * TILE_E + gm;
        ve = eg < E;
        sN = ve ? src[eg] : 0;
        dN = ve ? dst[eg] : 0;
        const float4* p = (const float4*)((gq < 2) ? (x + (size_t)sN * 64 + gq * 32)
                                                   : (x + (size_t)dN * 64 + (gq - 2) * 32));
        #pragma unroll
        for (int i = 0; i < 8; ++i) rc0[i] = p[i];
    }

    // ---------- one-time weight staging (whole block) ----------
    for (int i = tid; i < 128 * 232; i += NTHR) {
        const int j = i / 232, k = i - j * 232;
        const float v = (k < K1) ? W1[j * K1 + k] : 0.f;
        const u32 uv = __float_as_uint(v);
        *(u16*)(smem + OFF_W1H + j * STW1 + k * 2) = (u16)(uv >> 16);
        const float r = v - __uint_as_float(uv & 0xFFFF0000u);
        const __nv_bfloat16 rb = __float2bfloat16(r);
        *(u16*)(smem + OFF_W1L + j * STW1 + k * 2) = *(const u16*)&rb;
    }
    for (int i = tid; i < 32 * 136; i += NTHR) {
        const int j = i / 136, k = i - j * 136;
        const float v = (k < 128) ? W2[j * 128 + k] : 0.f;
        const u32 uv = __float_as_uint(v);
        *(u16*)(smem + OFF_W2H + j * STW2 + k * 2) = (u16)(uv >> 16);
        const float r = v - __uint_as_float(uv & 0xFFFF0000u);
        const __nv_bfloat16 rb = __float2bfloat16(r);
        *(u16*)(smem + OFF_W2L + j * STW2 + k * 2) = *(const u16*)&rb;
    }
    if (tid < 128) ((float*)(smem + OFF_B1S))[tid] = b1[tid];
    if (tid < 32)  ((float*)(smem + OFF_B2S))[tid] = b2[tid];
    if (tid < 64)  ((float*)(smem + OFF_W3S))[tid] = W3[tid];
    if (tid < 2)   ((float*)(smem + OFF_B3S))[tid] = b3[tid];

    // ---------- per-lane fragment addresses (group-local; warp = n-quarter) ----------
    const int nq = wg;            // n-quarter: layer1 cols nq*32 .. +31; layer2 cols nq*8
    const int aRow = ((lane >> 3) & 1) * 8 + (lane & 7);
    const u32 aOff = (u32)aRow * STA + (u32)(lane >> 4) * 16;
    const u32 aBH  = sb + aBase + aOff;
    const u32 aBL  = aBH + A_PART;
    const int bSel = lane >> 4, bKh = (lane >> 3) & 1, bRow = lane & 7;
    const u32 b1off = (u32)(nq * 32 + bSel * 8 + bRow) * STW1 + (u32)bKh * 16;
    const u32 b1H  = sb + OFF_W1H + b1off;
    const u32 b1L  = sb + OFF_W1L + b1off;
    const u32 b2off = (u32)(nq * 8 + (lane & 7)) * STW2 + (u32)((lane >> 3) & 1) * 16;
    const u32 b2H  = sb + OFF_W2H + b2off;
    const u32 b2L  = sb + OFF_W2L + b2off;

    const float* b1s = (const float*)(smem + OFF_B1S);
    const float* b2s = (const float*)(smem + OFF_B2S);
    const float* W3s = (const float*)(smem + OFF_W3S);
    const float* b3s = (const float*)(smem + OFF_B3S);
    float* h2s = (float*)(smem + OFF_H2 + g * 4352);   // [32][34] f32

    __syncthreads();   // weights staged (block-wide, once)

    #define GBAR() asm volatile("bar.sync %0, %1;" :: "r"(barid), "n"(128) : "memory")

    for (int tile = blockIdx.x * 4 + g; tile < ntiles; tile += gridDim.x * 4) {
        const int ebase = tile * TILE_E;
        const int  eg   = ebase + gm;
        const size_t egc = ve ? (size_t)eg : 0;

        // ---------- STS chunk0 from prefetched registers ----------
        {
            const float* v = (const float*)rc0;
            const u32 wb = (u32)gm * STA + (u32)gq * 64;
            #pragma unroll
            for (int t8 = 0; t8 < 4; ++t8)
                sts_split8(smem, aBase, wb + t8 * 16, v + 8 * t8);
        }

        // ---------- prefetch chunk1 -> registers ----------
        float4 rc1[8];
        if (gq < 2) {
            const float4* p = (const float4*)(efeat + egc * 64 + gq * 32);
            #pragma unroll
            for (int i = 0; i < 8; ++i) rc1[i] = p[i];
        } else if (gq == 2) {
            // nf_s(10) + nf_d(0..5): chunk1 cols 64..79
            float* v = (float*)rc1;
            #pragma unroll
            for (int j = 0; j < 10; ++j) v[j] = nodef[(size_t)sN * 10 + j];
            #pragma unroll
            for (int j = 0; j < 6; ++j)  v[10 + j] = nodef[(size_t)dN * 10 + j];
        } else {
            // nf_d(6..9) + ef(2) + pad: chunk1 cols 80..95
            float* v = (float*)rc1;
            #pragma unroll
            for (int j = 0; j < 4; ++j) v[j] = nodef[(size_t)dN * 10 + 6 + j];
            v[4] = edgef[egc * 2];
            v[5] = edgef[egc * 2 + 1];
            #pragma unroll
            for (int j = 6; j < 16; ++j) v[j] = 0.f;
        }
        GBAR();

        float acc[2][4][4];
        #pragma unroll
        for (int i = 0; i < 2; ++i)
            #pragma unroll
            for (int j = 0; j < 4; ++j)
                #pragma unroll
                for (int p = 0; p < 4; ++p) acc[i][j][p] = 0.f;

        l1_chunk<8>(acc, aBH, aBL, b1H, b1L, 0);
        GBAR();

        // ---------- STS chunk1 (A cols 0..95 reused for k=128..223) ----------
        if (gq < 2) {
            const float* v = (const float*)rc1;
            const u32 wb = (u32)gm * STA + (u32)gq * 64;
            #pragma unroll
            for (int t8 = 0; t8 < 4; ++t8)
                sts_split8(smem, aBase, wb + t8 * 16, v + 8 * t8);
        } else {
            const float* v = (const float*)rc1;
            const u32 wb = (u32)gm * STA + 128 + (u32)(gq - 2) * 32;
            #pragma unroll
            for (int t8 = 0; t8 < 2; ++t8)
                sts_split8(smem, aBase, wb + t8 * 16, v + 8 * t8);
        }
        GBAR();

        l1_chunk<6>(acc, aBH, aBL, b1H, b1L, 8 * 32);
        GBAR();

        // ---------- epilogue 1: bias + relu + split -> h1 into A buffers ----------
        #pragma unroll
        for (int mb = 0; mb < 2; ++mb) {
            const int r0 = mb * 16 + (lane >> 2);
            #pragma unroll
            for (int nbl = 0; nbl < 4; ++nbl) {
                const int n0 = nq * 32 + nbl * 8 + 2 * (lane & 3);
                const float bb0 = b1s[n0], bb1 = b1s[n0 + 1];
                float f0 = fmaxf(acc[mb][nbl][0] + bb0, 0.f);
                float f1 = fmaxf(acc[mb][nbl][1] + bb1, 0.f);
                u32 hp, lp;
                splitp(f0, f1, hp, lp);
                *(u32*)(smem + aBase + r0 * STA + n0 * 2) = hp;
                *(u32*)(smem + aBase + A_PART + r0 * STA + n0 * 2) = lp;
                f0 = fmaxf(acc[mb][nbl][2] + bb0, 0.f);
                f1 = fmaxf(acc[mb][nbl][3] + bb1, 0.f);
                splitp(f0, f1, hp, lp);
                *(u32*)(smem + aBase + (r0 + 8) * STA + n0 * 2) = hp;
                *(u32*)(smem + aBase + A_PART + (r0 + 8) * STA + n0 * 2) = lp;
            }
        }

        // ---------- prefetch next tile's chunk0 ----------
        {
            const int tn = tile + gridDim.x * 4;
            if (tn < ntiles) {
                const int eg2 = tn * TILE_E + gm;
                ve = eg2 < E;
                sN = ve ? src[eg2] : 0;
                dN = ve ? dst[eg2] : 0;
                const float4* p = (const float4*)((gq < 2) ? (x + (size_t)sN * 64 + gq * 32)
                                                           : (x + (size_t)dN * 64 + (gq - 2) * 32));
                #pragma unroll
                for (int i = 0; i < 8; ++i) rc0[i] = p[i];
            }
        }
        GBAR();

        // ---------- layer 2: h1[32x128] @ W2^T -> h2[32x32]; warp owns 32r x 8c ----------
        float acc2[2][4], acc2c[2][4];
        #pragma unroll
        for (int i = 0; i < 2; ++i)
            #pragma unroll
            for (int p = 0; p < 4; ++p) { acc2[i][p] = 0.f; acc2c[i][p] = 0.f; }

        #pragma unroll
        for (int ks = 0; ks < 8; ++ks) {
            u32 ah[2][4], al[2][4], bh[2], bl[2];
            #pragma unroll
            for (int mb = 0; mb < 2; ++mb) {
                ldm4(aBH + mb * (16 * STA) + ks * 32, ah[mb]);
                ldm4(aBL + mb * (16 * STA) + ks * 32, al[mb]);
            }
            ldm2(b2H + ks * 32, bh);
            ldm2(b2L + ks * 32, bl);
            #pragma unroll
            for (int mb = 0; mb < 2; ++mb) mma_bf16(acc2[mb],  ah[mb], bh[0], bh[1]);
            #pragma unroll
            for (int mb = 0; mb < 2; ++mb) mma_bf16(acc2c[mb], al[mb], bh[0], bh[1]);
            #pragma unroll
            for (int mb = 0; mb < 2; ++mb) mma_bf16(acc2c[mb], ah[mb], bl[0], bl[1]);
        }

        // ---------- epilogue 2: bias + relu -> h2s ----------
        #pragma unroll
        for (int mb = 0; mb < 2; ++mb) {
            const int r0 = mb * 16 + (lane >> 2);
            const int c0 = nq * 8 + 2 * (lane & 3);
            const float bb0 = b2s[c0], bb1 = b2s[c0 + 1];
            *(float2*)(h2s + r0 * 34 + c0) =
                make_float2(fmaxf(acc2[mb][0] + acc2c[mb][0] + bb0, 0.f),
                            fmaxf(acc2[mb][1] + acc2c[mb][1] + bb1, 0.f));
            *(float2*)(h2s + (r0 + 8) * 34 + c0) =
                make_float2(fmaxf(acc2[mb][2] + acc2c[mb][2] + bb0, 0.f),
                            fmaxf(acc2[mb][3] + acc2c[mb][3] + bb1, 0.f));
        }
        GBAR();

        // ---------- layer 3: h2[32x32] @ W3^T + b3 -> out ----------
        if (gt < TILE_E * 2) {
            const int row = gt >> 1, cls = gt & 1;
            float sum = b3s[cls];
            #pragma unroll
            for (int k = 0; k < 32; ++k)
                sum = fmaf(h2s[row * 34 + k], W3s[cls * 32 + k], sum);
            const int ego = ebase + row;
            if (ego < E) out[(size_t)ego * 2 + cls] = sum;
        }
        // no trailing barrier: next iteration's A STS conflicts only with layer-2
        // reads, ordered by the barrier above; h2s is rewritten only after the
        // next epilogue-2 (multiple group barriers away).
    }
    #undef GBAR
}

extern "C" void kernel_launch(void* const* d_in, const int* in_sizes, int n_in,
                              void* d_out, int out_size) {
    const float* x     = (const float*)d_in[0];
    const float* efeat = (const float*)d_in[1];
    const float* nodef = (const float*)d_in[2];
    const float* edgef = (const float*)d_in[3];
    const int*   src   = (const int*)d_in[4];
    const int*   dst   = (const int*)d_in[5];
    const float* W1    = (const float*)d_in[6];
    const float* b1    = (const float*)d_in[7];
    const float* W2    = (const float*)d_in[8];
    const float* b2    = (const float*)d_in[9];
    const float* W3    = (const float*)d_in[10];
    const float* b3    = (const float*)d_in[11];
    float* out = (float*)d_out;

    const int E      = in_sizes[4];
    const int ntiles = (E + TILE_E - 1) / TILE_E;

    cudaFuncSetAttribute(edge_mlp_hmma, cudaFuncAttributeMaxDynamicSharedMemorySize, SMEM_SZ);
    int grid = 152;
    const int need = (ntiles + 3) / 4;
    if (grid > need) grid = need;
    edge_mlp_hmma<<<grid, NTHR, SMEM_SZ>>>(x, efeat, nodef, edgef, src, dst,
                                           W1, b1, W2, b2, W3, b3, out, E, ntiles);
}

// round 12
// speedup vs baseline: 3.2199x; 1.0007x over previous
#include <cuda_runtime.h>
#include <cuda_bf16.h>
#include <cstdint>

typedef uint32_t u32;
typedef unsigned short u16;

#define NTHR   512
#define TILE_E 32          // per group (4 groups)
#define K1     214

#define STA  272           // A/h1 row stride bytes (136 bf16)
#define STW1 464           // W1 row stride (232 bf16)
#define STW2 272

#define A_PART   8704      // 32 rows * STA
#define OFF_B1S  0
#define OFF_B2S  512
#define OFF_W3S  640
#define OFF_B3S  896
#define OFF_A0   1024      // group g A: hi at OFF_A0+g*2*A_PART, lo at +A_PART
#define OFF_W1H  (OFF_A0 + 8 * A_PART)          // 70656
#define OFF_W1L  (OFF_W1H + 128 * STW1)         // 130048
#define OFF_W2H  (OFF_W1L + 128 * STW1)         // 189440
#define OFF_W2L  (OFF_W2H + 32 * STW2)          // 198144
#define OFF_H2   (OFF_W2L + 32 * STW2)          // 206848; per group +4352
#define SMEM_SZ  (OFF_H2 + 4 * 32 * 34 * 4)     // 224256 B

__device__ __forceinline__ u32 s2u(const void* p) {
    u32 a;
    asm("{ .reg .u64 t; cvta.to.shared.u64 t, %1; cvt.u32.u64 %0, t; }" : "=r"(a) : "l"(p));
    return a;
}
__device__ __forceinline__ void ldm4(u32 addr, u32* r) {
    asm volatile("ldmatrix.sync.aligned.m8n8.x4.shared.b16 {%0,%1,%2,%3}, [%4];"
                 : "=r"(r[0]), "=r"(r[1]), "=r"(r[2]), "=r"(r[3]) : "r"(addr));
}
__device__ __forceinline__ void ldm2(u32 addr, u32* r) {
    asm volatile("ldmatrix.sync.aligned.m8n8.x2.shared.b16 {%0,%1}, [%2];"
                 : "=r"(r[0]), "=r"(r[1]) : "r"(addr));
}
__device__ __forceinline__ void mma_bf16(float* c, const u32* a, u32 b0, u32 b1) {
    asm volatile("mma.sync.aligned.m16n8k16.row.col.f32.bf16.bf16.f32 "
                 "{%0,%1,%2,%3}, {%4,%5,%6,%7}, {%8,%9}, {%0,%1,%2,%3};"
                 : "+f"(c[0]), "+f"(c[1]), "+f"(c[2]), "+f"(c[3])
                 : "r"(a[0]), "r"(a[1]), "r"(a[2]), "r"(a[3]), "r"(b0), "r"(b1));
}
__device__ __forceinline__ u32 cvt2(float a, float b) {
    u32 r;
    asm("cvt.rn.bf16x2.f32 %0, %2, %1;" : "=r"(r) : "f"(a), "f"(b));
    return r;
}
__device__ __forceinline__ void splitp(float a, float b, u32& hp, u32& lp) {
    u32 ua = __float_as_uint(a), ub = __float_as_uint(b);
    hp = __byte_perm(ua, ub, 0x7632);
    float ra = a - __uint_as_float(ua & 0xFFFF0000u);
    float rb = b - __uint_as_float(ub & 0xFFFF0000u);
    lp = cvt2(ra, rb);
}
// split 8 floats and store 16B hi at base+wb, 16B lo at base+A_PART+wb
__device__ __forceinline__ void sts_split8(char* smem, u32 base, u32 wb, const float* v) {
    uint4 hv, lv;
    splitp(v[0], v[1], hv.x, lv.x);
    splitp(v[2], v[3], hv.y, lv.y);
    splitp(v[4], v[5], hv.z, lv.z);
    splitp(v[6], v[7], hv.w, lv.w);
    *(uint4*)(smem + base + wb) = hv;
    *(uint4*)(smem + base + A_PART + wb) = lv;
}

// layer-1 chunk, term-outer ordering; warp tile 32 rows x 32 cols
template <int NKS>
__device__ __forceinline__ void l1_chunk(float (&acc)[2][4][4],
                                         u32 aBH, u32 aBL,
                                         u32 b1H, u32 b1L, u32 bk)
{
    #pragma unroll
    for (int ks = 0; ks < NKS; ++ks) {
        u32 ah[2][4], al[2][4], bh[2][4], bl[2][4];
        #pragma unroll
        for (int mb = 0; mb < 2; ++mb) {
            ldm4(aBH + mb * (16 * STA) + ks * 32, ah[mb]);
            ldm4(aBL + mb * (16 * STA) + ks * 32, al[mb]);
        }
        #pragma unroll
        for (int np = 0; np < 2; ++np) {
            ldm4(b1H + np * (16 * STW1) + bk + ks * 32, bh[np]);
            ldm4(b1L + np * (16 * STW1) + bk + ks * 32, bl[np]);
        }
        #pragma unroll
        for (int np = 0; np < 2; ++np)
            #pragma unroll
            for (int mb = 0; mb < 2; ++mb) {
                mma_bf16(acc[mb][2 * np],     ah[mb], bh[np][0], bh[np][1]);
                mma_bf16(acc[mb][2 * np + 1], ah[mb], bh[np][2], bh[np][3]);
            }
        #pragma unroll
        for (int np = 0; np < 2; ++np)
            #pragma unroll
            for (int mb = 0; mb < 2; ++mb) {
                mma_bf16(acc[mb][2 * np],     al[mb], bh[np][0], bh[np][1]);
                mma_bf16(acc[mb][2 * np + 1], al[mb], bh[np][2], bh[np][3]);
            }
        #pragma unroll
        for (int np = 0; np < 2; ++np)
            #pragma unroll
            for (int mb = 0; mb < 2; ++mb) {
                mma_bf16(acc[mb][2 * np],     ah[mb], bl[np][0], bl[np][1]);
                mma_bf16(acc[mb][2 * np + 1], ah[mb], bl[np][2], bl[np][3]);
            }
    }
}

extern "C" __global__ void __launch_bounds__(NTHR, 1)
edge_mlp_hmma(const float* __restrict__ x, const float* __restrict__ efeat,
              const float* __restrict__ nodef, const float* __restrict__ edgef,
              const int* __restrict__ src, const int* __restrict__ dst,
              const float* __restrict__ W1, const float* __restrict__ b1,
              const float* __restrict__ W2, const float* __restrict__ b2,
              const float* __restrict__ W3, const float* __restrict__ b3,
              float* __restrict__ out, int E, int ntiles)
{
    extern __shared__ char smem[];
    const u32 sb   = s2u(smem);
    const int tid  = threadIdx.x;
    const int g    = tid >> 7;          // pipeline group 0..3
    const int gt   = tid & 127;         // thread within group
    const int wg   = gt >> 5;           // warp within group (0..3)
    const int lane = tid & 31;
    const int barid = g + 1;            // named barrier id for this group

    const u32 aBase = OFF_A0 + (u32)g * (2 * A_PART);   // hi base; lo = +A_PART

    const int gm = gt >> 2, gq = gt & 3;  // gather: 4 threads per edge (32 edges)

    // ---------- initial prefetch: this group's tile-0 chunk0 ----------
    int sN, dN;
    bool ve;
    float4 rc0[8];
    {
        const int eg = (blockIdx.x * 4 + g) * TILE_E + gm;
        ve = eg < E;
        sN = ve ? src[eg] : 0;
        dN = ve ? dst[eg] : 0;
        const float4* p = (const float4*)((gq < 2) ? (x + (size_t)sN * 64 + gq * 32)
                                                   : (x + (size_t)dN * 64 + (gq - 2) * 32));
        #pragma unroll
        for (int i = 0; i < 8; ++i) rc0[i] = p[i];
    }

    // ---------- one-time weight staging (whole block) ----------
    for (int i = tid; i < 128 * 232; i += NTHR) {
        const int j = i / 232, k = i - j * 232;
        const float v = (k < K1) ? W1[j * K1 + k] : 0.f;
        const u32 uv = __float_as_uint(v);
        *(u16*)(smem + OFF_W1H + j * STW1 + k * 2) = (u16)(uv >> 16);
        const float r = v - __uint_as_float(uv & 0xFFFF0000u);
        const __nv_bfloat16 rb = __float2bfloat16(r);
        *(u16*)(smem + OFF_W1L + j * STW1 + k * 2) = *(const u16*)&rb;
    }
    for (int i = tid; i < 32 * 136; i += NTHR) {
        const int j = i / 136, k = i - j * 136;
        const float v = (k < 128) ? W2[j * 128 + k] : 0.f;
        const u32 uv = __float_as_uint(v);
        *(u16*)(smem + OFF_W2H + j * STW2 + k * 2) = (u16)(uv >> 16);
        const float r = v - __uint_as_float(uv & 0xFFFF0000u);
        const __nv_bfloat16 rb = __float2bfloat16(r);
        *(u16*)(smem + OFF_W2L + j * STW2 + k * 2) = *(const u16*)&rb;
    }
    if (tid < 128) ((float*)(smem + OFF_B1S))[tid] = b1[tid];
    if (tid < 32)  ((float*)(smem + OFF_B2S))[tid] = b2[tid];
    if (tid < 64)  ((float*)(smem + OFF_W3S))[tid] = W3[tid];
    if (tid < 2)   ((float*)(smem + OFF_B3S))[tid] = b3[tid];

    // ---------- per-lane fragment addresses (group-local; warp = n-quarter) ----------
    const int nq = wg;            // n-quarter: layer1 cols nq*32 .. +31; layer2 cols nq*8
    const int aRow = ((lane >> 3) & 1) * 8 + (lane & 7);
    const u32 aOff = (u32)aRow * STA + (u32)(lane >> 4) * 16;
    const u32 aBH  = sb + aBase + aOff;
    const u32 aBL  = aBH + A_PART;
    const int bSel = lane >> 4, bKh = (lane >> 3) & 1, bRow = lane & 7;
    const u32 b1off = (u32)(nq * 32 + bSel * 8 + bRow) * STW1 + (u32)bKh * 16;
    const u32 b1H  = sb + OFF_W1H + b1off;
    const u32 b1L  = sb + OFF_W1L + b1off;
    const u32 b2off = (u32)(nq * 8 + (lane & 7)) * STW2 + (u32)((lane >> 3) & 1) * 16;
    const u32 b2H  = sb + OFF_W2H + b2off;
    const u32 b2L  = sb + OFF_W2L + b2off;

    const float* b1s = (const float*)(smem + OFF_B1S);
    const float* b2s = (const float*)(smem + OFF_B2S);
    const float* W3s = (const float*)(smem + OFF_W3S);
    const float* b3s = (const float*)(smem + OFF_B3S);
    float* h2s = (float*)(smem + OFF_H2 + g * 4352);   // [32][34] f32

    __syncthreads();   // weights staged (block-wide, once)

    #define GBAR() asm volatile("bar.sync %0, %1;" :: "r"(barid), "n"(128) : "memory")

    for (int tile = blockIdx.x * 4 + g; tile < ntiles; tile += gridDim.x * 4) {
        const int ebase = tile * TILE_E;
        const int  eg   = ebase + gm;
        const size_t egc = ve ? (size_t)eg : 0;

        // ---------- STS chunk0 from prefetched registers ----------
        {
            const float* v = (const float*)rc0;
            const u32 wb = (u32)gm * STA + (u32)gq * 64;
            #pragma unroll
            for (int t8 = 0; t8 < 4; ++t8)
                sts_split8(smem, aBase, wb + t8 * 16, v + 8 * t8);
        }

        // ---------- prefetch chunk1 -> registers ----------
        float4 rc1[8];
        if (gq < 2) {
            const float4* p = (const float4*)(efeat + egc * 64 + gq * 32);
            #pragma unroll
            for (int i = 0; i < 8; ++i) rc1[i] = p[i];
        } else if (gq == 2) {
            // nf_s(10) + nf_d(0..5): chunk1 cols 64..79
            float* v = (float*)rc1;
            #pragma unroll
            for (int j = 0; j < 10; ++j) v[j] = nodef[(size_t)sN * 10 + j];
            #pragma unroll
            for (int j = 0; j < 6; ++j)  v[10 + j] = nodef[(size_t)dN * 10 + j];
        } else {
            // nf_d(6..9) + ef(2) + pad: chunk1 cols 80..95
            float* v = (float*)rc1;
            #pragma unroll
            for (int j = 0; j < 4; ++j) v[j] = nodef[(size_t)dN * 10 + 6 + j];
            v[4] = edgef[egc * 2];
            v[5] = edgef[egc * 2 + 1];
            #pragma unroll
            for (int j = 6; j < 16; ++j) v[j] = 0.f;
        }
        GBAR();

        float acc[2][4][4];
        #pragma unroll
        for (int i = 0; i < 2; ++i)
            #pragma unroll
            for (int j = 0; j < 4; ++j)
                #pragma unroll
                for (int p = 0; p < 4; ++p) acc[i][j][p] = 0.f;

        l1_chunk<8>(acc, aBH, aBL, b1H, b1L, 0);
        GBAR();

        // ---------- STS chunk1 (A cols 0..95 reused for k=128..223) ----------
        if (gq < 2) {
            const float* v = (const float*)rc1;
            const u32 wb = (u32)gm * STA + (u32)gq * 64;
            #pragma unroll
            for (int t8 = 0; t8 < 4; ++t8)
                sts_split8(smem, aBase, wb + t8 * 16, v + 8 * t8);
        } else {
            const float* v = (const float*)rc1;
            const u32 wb = (u32)gm * STA + 128 + (u32)(gq - 2) * 32;
            #pragma unroll
            for (int t8 = 0; t8 < 2; ++t8)
                sts_split8(smem, aBase, wb + t8 * 16, v + 8 * t8);
        }
        GBAR();

        l1_chunk<6>(acc, aBH, aBL, b1H, b1L, 8 * 32);
        GBAR();

        // ---------- epilogue 1: bias + relu + split -> h1 into A buffers ----------
        #pragma unroll
        for (int mb = 0; mb < 2; ++mb) {
            const int r0 = mb * 16 + (lane >> 2);
            #pragma unroll
            for (int nbl = 0; nbl < 4; ++nbl) {
                const int n0 = nq * 32 + nbl * 8 + 2 * (lane & 3);
                const float bb0 = b1s[n0], bb1 = b1s[n0 + 1];
                float f0 = fmaxf(acc[mb][nbl][0] + bb0, 0.f);
                float f1 = fmaxf(acc[mb][nbl][1] + bb1, 0.f);
                u32 hp, lp;
                splitp(f0, f1, hp, lp);
                *(u32*)(smem + aBase + r0 * STA + n0 * 2) = hp;
                *(u32*)(smem + aBase + A_PART + r0 * STA + n0 * 2) = lp;
                f0 = fmaxf(acc[mb][nbl][2] + bb0, 0.f);
                f1 = fmaxf(acc[mb][nbl][3] + bb1, 0.f);
                splitp(f0, f1, hp, lp);
                *(u32*)(smem + aBase + (r0 + 8) * STA + n0 * 2) = hp;
                *(u32*)(smem + aBase + A_PART + (r0 + 8) * STA + n0 * 2) = lp;
            }
        }

        // ---------- prefetch next tile's chunk0 ----------
        {
            const int tn = tile + gridDim.x * 4;
            if (tn < ntiles) {
                const int eg2 = tn * TILE_E + gm;
                ve = eg2 < E;
                sN = ve ? src[eg2] : 0;
                dN = ve ? dst[eg2] : 0;
                const float4* p = (const float4*)((gq < 2) ? (x + (size_t)sN * 64 + gq * 32)
                                                           : (x + (size_t)dN * 64 + (gq - 2) * 32));
                #pragma unroll
                for (int i = 0; i < 8; ++i) rc0[i] = p[i];
            }
        }
        GBAR();

        // ---------- layer 2: h1[32x128] @ W2^T -> h2[32x32]; warp owns 32r x 8c ----------
        float acc2[2][4], acc2c[2][4];
        #pragma unroll
        for (int i = 0; i < 2; ++i)
            #pragma unroll
            for (int p = 0; p < 4; ++p) { acc2[i][p] = 0.f; acc2c[i][p] = 0.f; }

        #pragma unroll
        for (int ks = 0; ks < 8; ++ks) {
            u32 ah[2][4], al[2][4], bh[2], bl[2];
            #pragma unroll
            for (int mb = 0; mb < 2; ++mb) {
                ldm4(aBH + mb * (16 * STA) + ks * 32, ah[mb]);
                ldm4(aBL + mb * (16 * STA) + ks * 32, al[mb]);
            }
            ldm2(b2H + ks * 32, bh);
            ldm2(b2L + ks * 32, bl);
            #pragma unroll
            for (int mb = 0; mb < 2; ++mb) mma_bf16(acc2[mb],  ah[mb], bh[0], bh[1]);
            #pragma unroll
            for (int mb = 0; mb < 2; ++mb) mma_bf16(acc2c[mb], al[mb], bh[0], bh[1]);
            #pragma unroll
            for (int mb = 0; mb < 2; ++mb) mma_bf16(acc2c[mb], ah[mb], bl[0], bl[1]);
        }

        // ---------- epilogue 2: bias + relu -> h2s ----------
        #pragma unroll
        for (int mb = 0; mb < 2; ++mb) {
            const int r0 = mb * 16 + (lane >> 2);
            const int c0 = nq * 8 + 2 * (lane & 3);
            const float bb0 = b2s[c0], bb1 = b2s[c0 + 1];
            *(float2*)(h2s + r0 * 34 + c0) =
                make_float2(fmaxf(acc2[mb][0] + acc2c[mb][0] + bb0, 0.f),
                            fmaxf(acc2[mb][1] + acc2c[mb][1] + bb1, 0.f));
            *(float2*)(h2s + (r0 + 8) * 34 + c0) =
                make_float2(fmaxf(acc2[mb][2] + acc2c[mb][2] + bb0, 0.f),
                            fmaxf(acc2[mb][3] + acc2c[mb][3] + bb1, 0.f));
        }
        GBAR();

        // ---------- layer 3: h2[32x32] @ W3^T + b3 -> out ----------
        if (gt < TILE_E * 2) {
            const int row = gt >> 1, cls = gt & 1;
            float sum = b3s[cls];
            #pragma unroll
            for (int k = 0; k < 32; ++k)
                sum = fmaf(h2s[row * 34 + k], W3s[cls * 32 + k], sum);
            const int ego = ebase + row;
            if (ego < E) out[(size_t)ego * 2 + cls] = sum;
        }
        // no trailing barrier: next iteration's A STS conflicts only with layer-2
        // reads, ordered by the barrier above; h2s is rewritten only after the
        // next epilogue-2 (multiple group barriers away).
    }
    #undef GBAR
}

extern "C" void kernel_launch(void* const* d_in, const int* in_sizes, int n_in,
                              void* d_out, int out_size) {
    const float* x     = (const float*)d_in[0];
    const float* efeat = (const float*)d_in[1];
    const float* nodef = (const float*)d_in[2];
    const float* edgef = (const float*)d_in[3];
    const int*   src   = (const int*)d_in[4];
    const int*   dst   = (const int*)d_in[5];
    const float* W1    = (const float*)d_in[6];
    const float* b1    = (const float*)d_in[7];
    const float* W2    = (const float*)d_in[8];
    const float* b2    = (const float*)d_in[9];
    const float* W3    = (const float*)d_in[10];
    const float* b3    = (const float*)d_in[11];
    float* out = (float*)d_out;

    const int E      = in_sizes[4];
    const int ntiles = (E + TILE_E - 1) / TILE_E;

    cudaFuncSetAttribute(edge_mlp_hmma, cudaFuncAttributeMaxDynamicSharedMemorySize, SMEM_SZ);
    int grid = 152;
    const int need = (ntiles + 3) / 4;
    if (grid > need) grid = need;
    edge_mlp_hmma<<<grid, NTHR, SMEM_SZ>>>(x, efeat, nodef, edgef, src, dst,
                                           W1, b1, W2, b2, W3, b3, out, E, ntiles);
}